// round 10
// baseline (speedup 1.0000x reference)
#include <cuda_runtime.h>
#include <math.h>
#include <stdint.h>

// Problem constants
#define NROWS 4096
#define DIMK  1024
#define CC    16384
#define LDC1  (CC + 1)

// Output layout offsets (floats), tuple order flattened row-major
#define OFF_SI 0ULL                                  // logit_stu_img [N, C+1]
#define OFF_TI (OFF_SI + (size_t)NROWS * LDC1)       // logit_tea_img [N, C+1]
#define OFF_ST (OFF_TI + (size_t)NROWS * LDC1)       // logit_stu_text [N, C]
#define OFF_TT (OFF_ST + (size_t)NROWS * CC)         // logit_tea_text [N, C]
#define OFF_S  (OFF_TT + (size_t)NROWS * CC)         // s [N, DIM]
#define OFF_T  (OFF_S  + (size_t)NROWS * DIMK)       // t [N, DIM]
#define OFF_Q  (OFF_T  + (size_t)NROWS * DIMK)       // new_queue [DIM, C]
#define OFF_P  (OFF_Q  + (size_t)DIMK * CC)          // new_ptr [C]

#define NBLK 64   // teacher GEMM n-tiles (CC/256)
#define MAXC 32   // refine candidate cap

// Scratch (static device globals; no allocation).
// Self-cleaning invariant: g_sums/g_counts/g_tmax_i/g_cmax_i are zero at the
// start of every kernel_launch (zero-initialized at load; reset by the last
// reader each run).
__device__ __align__(16) float g_sums[(size_t)DIMK * CC];   // [DIM][C]
__device__ float g_counts[CC];
__device__ int   g_labels[NROWS];
__device__ float g_pmax[(size_t)NROWS * NBLK * 2];
__device__ int   g_parg[(size_t)NROWS * NBLK * 2];
__device__ int   g_tmax_i;   // bits of max|t| (positive floats: int-monotone)
__device__ int   g_cmax_i;   // bits of max|classifier|

// ---------------------------------------------------------------------------
// helpers
// ---------------------------------------------------------------------------
__device__ __forceinline__ uint32_t f16x2_pack(float lo, float hi) {
    uint32_t r;
    asm("cvt.rn.f16x2.f32 %0, %1, %2;" : "=r"(r) : "f"(hi), "f"(lo));
    return r;
}

__device__ __forceinline__ void mma16(float* c, const uint4& a, uint32_t b0, uint32_t b1) {
    asm volatile(
        "mma.sync.aligned.m16n8k16.row.col.f32.f16.f16.f32 "
        "{%0,%1,%2,%3}, {%4,%5,%6,%7}, {%8,%9}, {%0,%1,%2,%3};\n"
        : "+f"(c[0]), "+f"(c[1]), "+f"(c[2]), "+f"(c[3])
        : "r"(a.x), "r"(a.y), "r"(a.z), "r"(a.w), "r"(b0), "r"(b1));
}

__device__ __forceinline__ void imma32(int* c, const uint4& a, uint32_t b0, uint32_t b1) {
    asm volatile(
        "mma.sync.aligned.m16n8k32.row.col.s32.s8.s8.s32 "
        "{%0,%1,%2,%3}, {%4,%5,%6,%7}, {%8,%9}, {%0,%1,%2,%3};\n"
        : "+r"(c[0]), "+r"(c[1]), "+r"(c[2]), "+r"(c[3])
        : "r"(a.x), "r"(a.y), "r"(a.z), "r"(a.w), "r"(b0), "r"(b1));
}

// pack 4 floats -> 4 saturated s8 bytes (byte0 = v.x = lowest k)
__device__ __forceinline__ uint32_t quant4(float x, float y, float z, float w, float s) {
    int a0 = __float2int_rn(x * s);
    int a1 = __float2int_rn(y * s);
    int a2 = __float2int_rn(z * s);
    int a3 = __float2int_rn(w * s);
    uint32_t r;
    asm("cvt.pack.sat.s8.s32.b32 %0, %1, %2, 0;" : "=r"(r) : "r"(a3), "r"(a2));
    asm("cvt.pack.sat.s8.s32.b32 %0, %1, %2, %0;" : "+r"(r) : "r"(a1), "r"(a0));
    return r;
}

struct Top2 { float v1, v2; int c1, c2; };
__device__ __forceinline__ void t2_init(Top2& t) {
    t.v1 = -3.4e38f; t.v2 = -3.4e38f; t.c1 = 0x7fffffff; t.c2 = 0x7fffffff;
}
__device__ __forceinline__ void t2_upd(Top2& t, float v, int c) {
    if (v > t.v1 || (v == t.v1 && c < t.c1)) {
        t.v2 = t.v1; t.c2 = t.c1; t.v1 = v; t.c1 = c;
    } else if (v > t.v2 || (v == t.v2 && c < t.c2)) {
        t.v2 = v; t.c2 = c;
    }
}
__device__ __forceinline__ void t2_merge_shfl(Top2& t, int d) {
    float ov1 = __shfl_xor_sync(0xffffffffu, t.v1, d);
    int   oc1 = __shfl_xor_sync(0xffffffffu, t.c1, d);
    float ov2 = __shfl_xor_sync(0xffffffffu, t.v2, d);
    int   oc2 = __shfl_xor_sync(0xffffffffu, t.c2, d);
    t2_upd(t, ov1, oc1);
    t2_upd(t, ov2, oc2);
}

// ---------------------------------------------------------------------------
// Kernel 1: row-normalize s,t; write s,t; positive logit col 0; max|t| atomic
// ---------------------------------------------------------------------------
__global__ void norm_kernel(const float* __restrict__ sr,
                            const float* __restrict__ tr,
                            float* __restrict__ out) {
    int n = blockIdx.x;
    int tid = threadIdx.x;
    const float4* s4 = (const float4*)(sr + (size_t)n * DIMK);
    const float4* t4 = (const float4*)(tr + (size_t)n * DIMK);
    float4 a = s4[tid];
    float4 b = t4[tid];
    float ss = a.x * a.x + a.y * a.y + a.z * a.z + a.w * a.w;
    float tt = b.x * b.x + b.y * b.y + b.z * b.z + b.w * b.w;
    float st = a.x * b.x + a.y * b.y + a.z * b.z + a.w * b.w;

    __shared__ float r0[256], r1[256], r2[256];
    r0[tid] = ss; r1[tid] = tt; r2[tid] = st;
    __syncthreads();
    #pragma unroll
    for (int s = 128; s > 0; s >>= 1) {
        if (tid < s) { r0[tid] += r0[tid + s]; r1[tid] += r1[tid + s]; r2[tid] += r2[tid + s]; }
        __syncthreads();
    }
    float ns = sqrtf(r0[0]);
    float nt = sqrtf(r1[0]);
    float inv_s = 1.0f / fmaxf(ns, 1e-12f);
    float inv_t = 1.0f / fmaxf(nt, 1e-12f);

    float4 so = make_float4(a.x * inv_s, a.y * inv_s, a.z * inv_s, a.w * inv_s);
    float4 to = make_float4(b.x * inv_t, b.y * inv_t, b.z * inv_t, b.w * inv_t);
    ((float4*)(out + OFF_S + (size_t)n * DIMK))[tid] = so;
    ((float4*)(out + OFF_T + (size_t)n * DIMK))[tid] = to;

    // max|t| for int8 teacher quantization
    float am = fmaxf(fmaxf(fabsf(to.x), fabsf(to.y)), fmaxf(fabsf(to.z), fabsf(to.w)));
    #pragma unroll
    for (int d = 16; d > 0; d >>= 1)
        am = fmaxf(am, __shfl_xor_sync(0xffffffffu, am, d));
    if ((tid & 31) == 0)
        atomicMax(&g_tmax_i, __float_as_int(am));

    if (tid == 0) {
        float sp = r2[0] * inv_s * inv_t;
        out[OFF_SI + (size_t)n * LDC1] = sp * (1.0f / 0.07f);
    }
}

// ---------------------------------------------------------------------------
// Kernel 2: max|classifier| scan (for int8 quantization scale)
// ---------------------------------------------------------------------------
__global__ void max_cls(const float* __restrict__ cls) {
    size_t n4 = (size_t)DIMK * CC / 4;
    const float4* p = (const float4*)cls;
    float m = 0.0f;
    for (size_t i = (size_t)blockIdx.x * blockDim.x + threadIdx.x; i < n4;
         i += (size_t)gridDim.x * blockDim.x) {
        float4 v = p[i];
        m = fmaxf(m, fmaxf(fmaxf(fabsf(v.x), fabsf(v.y)), fmaxf(fabsf(v.z), fabsf(v.w))));
    }
    #pragma unroll
    for (int d = 16; d > 0; d >>= 1)
        m = fmaxf(m, __shfl_xor_sync(0xffffffffu, m, d));
    if ((threadIdx.x & 31) == 0)
        atomicMax(&g_cmax_i, __float_as_int(m));
}

// ---------------------------------------------------------------------------
// Kernel 4: FP16 mma GEMM (students), CTA 128x256, warp 64x64, 8 warps.
// ZMODE: 0 = none, 1 = also zero-fill zbase region [N*CC], 2 = also fill
// zbase region [N*LDC1] with one-hot col0 (tea_img). The fill stores are
// fire-and-forget and ride on DRAM left idle by the compute-bound mainloop.
// ---------------------------------------------------------------------------
#define TBUF 24576
#define TOB  8192

template<int ZMODE>
__global__ __launch_bounds__(256, 1)
void gemm_fp16(const float* __restrict__ A, const float* __restrict__ B,
               float* __restrict__ Cout, int ldc, float scale,
               float* __restrict__ zbase) {
    extern __shared__ char smc[];

    const int tid  = threadIdx.x;
    const int lane = tid & 31;
    const int wid  = tid >> 5;
    const int wm   = wid & 1;
    const int wn   = wid >> 1;
    const int mbase = blockIdx.y * 128;
    const int nbase = blockIdx.x * 256;

    // folded output-region fill (overlaps with the tensor mainloop)
    if (ZMODE == 1) {
        size_t total4 = (size_t)NROWS * CC / 4;
        size_t cta = (size_t)blockIdx.y * gridDim.x + blockIdx.x;
        const size_t zstride = (size_t)2048 * 256;
        float4 z = make_float4(0.f, 0.f, 0.f, 0.f);
        for (size_t i = cta * 256 + tid; i < total4; i += zstride)
            ((float4*)zbase)[i] = z;
    } else if (ZMODE == 2) {
        size_t total4 = (size_t)NROWS * LDC1 / 4;
        size_t cta = (size_t)blockIdx.y * gridDim.x + blockIdx.x;
        const size_t zstride = (size_t)2048 * 256;
        size_t zi = cta * 256 + tid;
        unsigned int m = (unsigned int)((4 * zi) % LDC1);
        const unsigned int inc = (unsigned int)((4 * zstride) % LDC1);
        for (size_t i = zi; i < total4; i += zstride) {
            float4 v = make_float4(0.f, 0.f, 0.f, 0.f);
            unsigned int j = (m == 0) ? 0u : (unsigned int)LDC1 - m;
            if (j < 4) (&v.x)[j] = 1.0f;
            ((float4*)zbase)[i] = v;
            m += inc; if (m >= (unsigned int)LDC1) m -= (unsigned int)LDC1;
        }
    }

    // A fill meta: idx -> (m, k4); f16x2 words are k-pairs
    int baseA[4], slA[4], swA[4];
    const float* aptr[4];
    #pragma unroll
    for (int q = 0; q < 4; q++) {
        int idx = tid + 256 * q;
        int m = idx >> 3, k4 = (idx & 7) * 4;
        aptr[q] = A + (size_t)(mbase + m) * DIMK + k4;
        int fm = m >> 4, mr = m & 15, fk = k4 >> 4;
        int r0 = ((mr >> 3) & 1) + ((k4 & 8) ? 2 : 0);
        baseA[q] = (fk * 8 + fm) * 512 + r0 * 4;
        slA[q] = ((mr & 7) * 4 + ((k4 & 7) >> 1)) * 16;
        swA[q] = fk << 4;
    }
    // B fill meta: idx -> (kpair kp, n4); words pack two k-rows at one n
    int baseB[4], slB[4], swB[4];
    const float* bptr[4];
    #pragma unroll
    for (int q = 0; q < 4; q++) {
        int idx = tid + 256 * q;
        int kp = idx >> 6, n4 = (idx & 63) * 4;
        bptr[q] = B + (size_t)(2 * kp) * CC + nbase + n4;
        int fn2 = n4 >> 4, fnb = (n4 >> 3) & 1, fk = kp >> 3;
        baseB[q] = TOB + (fk * 16 + fn2) * 512 + (fnb * 2 + ((kp >> 2) & 1)) * 4;
        slB[q] = ((n4 & 7) * 4 + (kp & 3)) * 16;
        swB[q] = (fn2 & 7) << 4;
    }

    float c[4][8][4];
    #pragma unroll
    for (int i = 0; i < 4; i++)
        #pragma unroll
        for (int j = 0; j < 8; j++)
            #pragma unroll
            for (int r = 0; r < 4; r++) c[i][j][r] = 0.0f;

    const int lane16 = lane * 16;

    float4 ra[4], rb0[4], rb1[4];

    // prologue
    #pragma unroll
    for (int q = 0; q < 4; q++) {
        ra[q]  = *(const float4*)aptr[q];
        rb0[q] = *(const float4*)bptr[q];
        rb1[q] = *(const float4*)(bptr[q] + CC);
    }
    {
        char* buf = smc;
        #pragma unroll
        for (int q = 0; q < 4; q++) {
            *(uint32_t*)(buf + baseA[q] + ((slA[q])      ^ swA[q])) = f16x2_pack(ra[q].x, ra[q].y);
            *(uint32_t*)(buf + baseA[q] + ((slA[q] + 16) ^ swA[q])) = f16x2_pack(ra[q].z, ra[q].w);
            float l0[4] = {rb0[q].x, rb0[q].y, rb0[q].z, rb0[q].w};
            float l1[4] = {rb1[q].x, rb1[q].y, rb1[q].z, rb1[q].w};
            #pragma unroll
            for (int j = 0; j < 4; j++)
                *(uint32_t*)(buf + baseB[q] + ((slB[q] + j * 64) ^ swB[q])) = f16x2_pack(l0[j], l1[j]);
        }
    }
    __syncthreads();

    for (int kt = 0; kt < 32; kt++) {
        char* cur = smc + (kt & 1) * TBUF;
        char* nxt = smc + ((kt & 1) ^ 1) * TBUF;
        if (kt < 31) {
            int kb = (kt + 1) * 32;
            #pragma unroll
            for (int q = 0; q < 4; q++) {
                ra[q]  = *(const float4*)(aptr[q] + kb);
                rb0[q] = *(const float4*)(bptr[q] + (size_t)kb * CC);
                rb1[q] = *(const float4*)(bptr[q] + (size_t)(kb + 1) * CC);
            }
        }
        #pragma unroll
        for (int fk = 0; fk < 2; fk++) {
            uint4 ahf[4], bhf[4];
            #pragma unroll
            for (int i = 0; i < 4; i++) {
                int off = (fk * 8 + wm * 4 + i) * 512 + (lane16 ^ (fk << 4));
                ahf[i] = *(const uint4*)(cur + off);
            }
            #pragma unroll
            for (int j = 0; j < 4; j++) {
                int fn2 = 4 * wn + j;
                int off = TOB + (fk * 16 + fn2) * 512 + (lane16 ^ ((fn2 & 7) << 4));
                bhf[j] = *(const uint4*)(cur + off);
            }
            #pragma unroll
            for (int i = 0; i < 4; i++)
                #pragma unroll
                for (int j = 0; j < 4; j++) {
                    mma16(c[i][2 * j],     ahf[i], bhf[j].x, bhf[j].y);
                    mma16(c[i][2 * j + 1], ahf[i], bhf[j].z, bhf[j].w);
                }
        }
        if (kt < 31) {
            #pragma unroll
            for (int q = 0; q < 4; q++) {
                *(uint32_t*)(nxt + baseA[q] + ((slA[q])      ^ swA[q])) = f16x2_pack(ra[q].x, ra[q].y);
                *(uint32_t*)(nxt + baseA[q] + ((slA[q] + 16) ^ swA[q])) = f16x2_pack(ra[q].z, ra[q].w);
                float l0[4] = {rb0[q].x, rb0[q].y, rb0[q].z, rb0[q].w};
                float l1[4] = {rb1[q].x, rb1[q].y, rb1[q].z, rb1[q].w};
                #pragma unroll
                for (int j = 0; j < 4; j++)
                    *(uint32_t*)(nxt + baseB[q] + ((slB[q] + j * 64) ^ swB[q])) = f16x2_pack(l0[j], l1[j]);
            }
        }
        __syncthreads();
    }

    // C frag mapping: rows wm*64 + i*16 + (lane>>2) (+8),
    // cols wn*64 + jn*8 + (lane&3)*2 (+1)
    #pragma unroll
    for (int i = 0; i < 4; i++) {
        int r0 = mbase + wm * 64 + i * 16 + (lane >> 2);
        #pragma unroll
        for (int jn = 0; jn < 8; jn++) {
            int col = nbase + wn * 64 + jn * 8 + (lane & 3) * 2;
            size_t o = (size_t)r0 * ldc + col;
            Cout[o]     = c[i][jn][0] * scale;
            Cout[o + 1] = c[i][jn][1] * scale;
            size_t o2 = o + (size_t)8 * ldc;
            Cout[o2]     = c[i][jn][2] * scale;
            Cout[o2 + 1] = c[i][jn][3] * scale;
        }
    }
}

// ---------------------------------------------------------------------------
// Kernel 4b: INT8 screening GEMM (teacher). CTA 128x256, warp 64x64, 8 warps.
// mma.m16n8k32.s8 (2x fp16 rate); s32 accumulation is exact; only input
// quantization error (sigma ~0.016) vs the 0.15 refine window.
// No C writes; per-row TOP-2 (val,col) partials to g_pmax/g_parg.
// SMEM: stage = A 4KB + B 8KB = 12KB, double buffered (24KB).
// ---------------------------------------------------------------------------
#define S8BUF 12288
#define S8OB  4096

__global__ __launch_bounds__(256, 1)
void gemm_s8_top2(const float* __restrict__ A, const float* __restrict__ B) {
    extern __shared__ char smc[];

    const int tid  = threadIdx.x;
    const int lane = tid & 31;
    const int wid  = tid >> 5;
    const int wm   = wid & 1;
    const int wn   = wid >> 1;
    const int mbase = blockIdx.y * 128;
    const int nbase = blockIdx.x * 256;

    const float gt = __int_as_float(g_tmax_i);
    const float gc = __int_as_float(g_cmax_i);
    const float sa = 126.0f / fmaxf(gt, 1e-20f);
    const float sb = 126.0f / fmaxf(gc, 1e-20f);
    const float invs = 1.0f / (sa * sb);

    // A fill meta: idx = tid+256q (q<4): m = idx>>3, kq = idx&7 (k-quad)
    // word (row mr, kq) in frag fm: byte = ((mr&7)*4+(kq&3))*16 + ((mr>>3)+2*(kq>>2))*4
    int offA[4];
    const float* aptr[4];
    #pragma unroll
    for (int q = 0; q < 4; q++) {
        int idx = tid + 256 * q;
        int m = idx >> 3, kq = idx & 7;
        aptr[q] = A + (size_t)(mbase + m) * DIMK + kq * 4;
        int fm = m >> 4, mr = m & 15;
        offA[q] = fm * 512 + ((mr & 7) * 4 + (kq & 3)) * 16 + ((mr >> 3) + 2 * (kq >> 2)) * 4;
    }
    // B fill meta: idx = tid+256q (q<2): kq = idx>>6, n4 = (idx&63)*4
    // word (n, kq): pair p = n>>4, side = (n>>3)&1:
    //   off = S8OB + p*512 + ((((n&7)*4+(kq&3))*16 + (side*2+(kq>>2))*4) ^ ((p&7)<<4))
    int offB[2][4];
    const float* bptr[2];
    #pragma unroll
    for (int q = 0; q < 2; q++) {
        int idx = tid + 256 * q;
        int kq = idx >> 6, n4 = (idx & 63) * 4;
        bptr[q] = B + (size_t)(kq * 4) * CC + nbase + n4;
        #pragma unroll
        for (int j = 0; j < 4; j++) {
            int n = n4 + j;
            int p = n >> 4, side = (n >> 3) & 1;
            int byteoff = ((n & 7) * 4 + (kq & 3)) * 16 + (side * 2 + (kq >> 2)) * 4;
            offB[q][j] = S8OB + p * 512 + (byteoff ^ ((p & 7) << 4));
        }
    }

    int c[4][8][4];
    #pragma unroll
    for (int i = 0; i < 4; i++)
        #pragma unroll
        for (int j = 0; j < 8; j++)
            #pragma unroll
            for (int r = 0; r < 4; r++) c[i][j][r] = 0;

    const int lane16 = lane * 16;

    float4 ra[4], rb[2][4];

    // prologue: chunk 0 loads + quantized stores into buffer 0
    #pragma unroll
    for (int q = 0; q < 4; q++) ra[q] = *(const float4*)aptr[q];
    #pragma unroll
    for (int q = 0; q < 2; q++)
        #pragma unroll
        for (int r = 0; r < 4; r++)
            rb[q][r] = *(const float4*)(bptr[q] + (size_t)r * CC);
    {
        char* buf = smc;
        #pragma unroll
        for (int q = 0; q < 4; q++)
            *(uint32_t*)(buf + offA[q]) = quant4(ra[q].x, ra[q].y, ra[q].z, ra[q].w, sa);
        #pragma unroll
        for (int q = 0; q < 2; q++)
            #pragma unroll
            for (int j = 0; j < 4; j++) {
                const float* f0 = &rb[q][0].x;
                const float* f1 = &rb[q][1].x;
                const float* f2 = &rb[q][2].x;
                const float* f3 = &rb[q][3].x;
                *(uint32_t*)(buf + offB[q][j]) = quant4(f0[j], f1[j], f2[j], f3[j], sb);
            }
    }
    __syncthreads();

    for (int kt = 0; kt < 32; kt++) {
        char* cur = smc + (kt & 1) * S8BUF;
        char* nxt = smc + ((kt & 1) ^ 1) * S8BUF;
        if (kt < 31) {
            int kb = (kt + 1) * 32;
            #pragma unroll
            for (int q = 0; q < 4; q++) ra[q] = *(const float4*)(aptr[q] + kb);
            #pragma unroll
            for (int q = 0; q < 2; q++)
                #pragma unroll
                for (int r = 0; r < 4; r++)
                    rb[q][r] = *(const float4*)(bptr[q] + (size_t)(kb + r) * CC);
        }
        // compute: one k32 step covers the whole chunk
        {
            uint4 af[4], bf[4];
            #pragma unroll
            for (int i = 0; i < 4; i++)
                af[i] = *(const uint4*)(cur + (wm * 4 + i) * 512 + lane16);
            #pragma unroll
            for (int j = 0; j < 4; j++) {
                int p = 4 * wn + j;
                bf[j] = *(const uint4*)(cur + S8OB + p * 512 + (lane16 ^ ((p & 7) << 4)));
            }
            #pragma unroll
            for (int i = 0; i < 4; i++)
                #pragma unroll
                for (int j = 0; j < 4; j++) {
                    imma32(c[i][2 * j],     af[i], bf[j].x, bf[j].y);
                    imma32(c[i][2 * j + 1], af[i], bf[j].z, bf[j].w);
                }
        }
        if (kt < 31) {
            #pragma unroll
            for (int q = 0; q < 4; q++)
                *(uint32_t*)(nxt + offA[q]) = quant4(ra[q].x, ra[q].y, ra[q].z, ra[q].w, sa);
            #pragma unroll
            for (int q = 0; q < 2; q++)
                #pragma unroll
                for (int j = 0; j < 4; j++) {
                    const float* f0 = &rb[q][0].x;
                    const float* f1 = &rb[q][1].x;
                    const float* f2 = &rb[q][2].x;
                    const float* f3 = &rb[q][3].x;
                    *(uint32_t*)(nxt + offB[q][j]) = quant4(f0[j], f1[j], f2[j], f3[j], sb);
                }
        }
        __syncthreads();
    }

    // top-2 per row over this 128x256 tile (C frag mapping same as fp16)
    float* rv1 = (float*)smc;
    int*   rc1 = (int*)(smc + 2048);
    float* rv2 = (float*)(smc + 4096);
    int*   rc2 = (int*)(smc + 6144);
    #pragma unroll
    for (int i = 0; i < 4; i++) {
        Top2 a, b;
        t2_init(a); t2_init(b);
        #pragma unroll
        for (int jn = 0; jn < 8; jn++) {
            int col = wn * 64 + jn * 8 + (lane & 3) * 2;
            t2_upd(a, (float)c[i][jn][0] * invs, col);
            t2_upd(a, (float)c[i][jn][1] * invs, col + 1);
            t2_upd(b, (float)c[i][jn][2] * invs, col);
            t2_upd(b, (float)c[i][jn][3] * invs, col + 1);
        }
        t2_merge_shfl(a, 1); t2_merge_shfl(a, 2);
        t2_merge_shfl(b, 1); t2_merge_shfl(b, 2);
        if ((lane & 3) == 0) {
            int rA = wm * 64 + i * 16 + (lane >> 2);
            rv1[rA * 4 + wn] = a.v1; rc1[rA * 4 + wn] = a.c1;
            rv2[rA * 4 + wn] = a.v2; rc2[rA * 4 + wn] = a.c2;
            int rB = rA + 8;
            rv1[rB * 4 + wn] = b.v1; rc1[rB * 4 + wn] = b.c1;
            rv2[rB * 4 + wn] = b.v2; rc2[rB * 4 + wn] = b.c2;
        }
    }
    __syncthreads();
    if (tid < 128) {
        Top2 t;
        t2_init(t);
        #pragma unroll
        for (int w = 0; w < 4; w++) {
            t2_upd(t, rv1[tid * 4 + w], rc1[tid * 4 + w]);
            t2_upd(t, rv2[tid * 4 + w], rc2[tid * 4 + w]);
        }
        size_t o = ((size_t)(mbase + tid) * NBLK + blockIdx.x) * 2;
        g_pmax[o]     = t.v1;  g_parg[o]     = nbase + t.c1;
        g_pmax[o + 1] = t.v2;  g_parg[o + 1] = nbase + t.c2;
    }
}

// ---------------------------------------------------------------------------
// Kernel 5: candidate refine. int8 top-2 partials -> threshold max-0.15
// (>8 sigma of int8 quantization error) -> exact fp32 re-dot -> exact argmax
// + exact softmax over survivors (others underflow to exact fp32 zero).
// ---------------------------------------------------------------------------
__global__ void argmax_refine(const float* __restrict__ t,
                              const float* __restrict__ cls,
                              float* __restrict__ out) {
    int n = blockIdx.x;
    int tid = threadIdx.x;
    __shared__ float pv[NBLK * 2];
    __shared__ int   pi[NBLK * 2];
    for (int i = tid; i < NBLK * 2; i += 256) {
        pv[i] = g_pmax[(size_t)n * NBLK * 2 + i];
        pi[i] = g_parg[(size_t)n * NBLK * 2 + i];
    }
    __syncthreads();
    __shared__ int cand[MAXC];
    __shared__ int ncand_s;
    if (tid == 0) {
        float m = -3.4e38f;
        for (int i = 0; i < NBLK * 2; i++) m = fmaxf(m, pv[i]);
        float thr = m - 0.15f;
        int nc = 0;
        for (int i = 0; i < NBLK * 2 && nc < MAXC; i++)
            if (pv[i] >= thr) cand[nc++] = pi[i];
        ncand_s = nc;
    }
    __syncthreads();
    int nc = ncand_s;

    __shared__ float ev[MAXC];
    __shared__ float red[256];
    const float* trow = t + (size_t)n * DIMK;
    for (int k = 0; k < nc; k++) {
        int col = cand[k];
        float part = 0.0f;
        for (int d = tid; d < DIMK; d += 256)
            part += trow[d] * cls[(size_t)d * CC + col];
        red[tid] = part;
        __syncthreads();
        #pragma unroll
        for (int s = 128; s > 0; s >>= 1) {
            if (tid < s) red[tid] += red[tid + s];
            __syncthreads();
        }
        if (tid == 0) ev[k] = red[0];
        __syncthreads();
    }

    if (tid == 0) {
        float v1 = -3.4e38f;
        int best = 0x7fffffff;
        for (int k = 0; k < nc; k++) {
            if (ev[k] > v1 || (ev[k] == v1 && cand[k] < best)) { v1 = ev[k]; best = cand[k]; }
        }
        g_labels[n] = best;
        float x1 = v1 / 1e-4f;
        float sum = 0.0f;
        for (int k = 0; k < nc; k++)
            sum += expf(ev[k] / 1e-4f - x1);
        float inv = 1.0f / sum;
        for (int k = 0; k < nc; k++)
            out[OFF_TT + (size_t)n * CC + cand[k]] = expf(ev[k] / 1e-4f - x1) * inv;
    }
}

// ---------------------------------------------------------------------------
// Kernel 6: scatter t rows into per-cluster sums/counts
// ---------------------------------------------------------------------------
__global__ void scatter_kernel(const float* __restrict__ t) {
    int n = blockIdx.x;
    int lab = g_labels[n];
    const float* trow = t + (size_t)n * DIMK;
    for (int d = threadIdx.x; d < DIMK; d += 256)
        atomicAdd(&g_sums[(size_t)d * CC + lab], trow[d]);
    if (threadIdx.x == 0)
        atomicAdd(&g_counts[lab], 1.0f);
}

// ---------------------------------------------------------------------------
// Kernel 7: EMA queue update -> new_queue [DIM, C]; resets g_sums to zero
// (self-cleaning scratch: avoids a dedicated 64MB zero pass next run)
// ---------------------------------------------------------------------------
__global__ void update_queue(const float* __restrict__ queue,
                             const int* __restrict__ qptr,
                             float* __restrict__ outq) {
    size_t idx = (size_t)blockIdx.x * blockDim.x + threadIdx.x;
    int c = (int)(idx & (CC - 1));
    float cnt = g_counts[c];
    float q = queue[idx];
    float sv = g_sums[idx];
    g_sums[idx] = 0.0f;
    float z = sv / fmaxf(cnt, 1.0f);
    bool present = cnt > 0.0f;
    bool init = qptr[c] > 0;
    float ema = 0.99f * q + 0.01f * z;
    float ncol = init ? ema : z;
    outq[idx] = present ? ncol : q;
}

// ---------------------------------------------------------------------------
// Kernel 8: new_ptr; resets g_counts and the quantization maxima
// ---------------------------------------------------------------------------
__global__ void update_ptr(const int* __restrict__ qptr, float* __restrict__ outp) {
    int c = blockIdx.x * blockDim.x + threadIdx.x;
    if (c < CC) {
        float cnt = g_counts[c];
        outp[c] = (cnt > 0.0f) ? 1.0f : (float)qptr[c];
        g_counts[c] = 0.0f;
    }
    if (c == 0) { g_tmax_i = 0; g_cmax_i = 0; }
}

// ---------------------------------------------------------------------------
extern "C" void kernel_launch(void* const* d_in, const int* in_sizes, int n_in,
                              void* d_out, int out_size) {
    const float* s_raw      = (const float*)d_in[0];
    const float* t_raw      = (const float*)d_in[1];
    const float* queue      = (const float*)d_in[2];
    const float* classifier = (const float*)d_in[3];
    const int*   qptr       = (const int*)d_in[4];
    float* out = (float*)d_out;

    cudaFuncSetAttribute(gemm_fp16<1>,
                         cudaFuncAttributeMaxDynamicSharedMemorySize, 2 * TBUF);
    cudaFuncSetAttribute(gemm_fp16<2>,
                         cudaFuncAttributeMaxDynamicSharedMemorySize, 2 * TBUF);

    norm_kernel<<<NROWS, 256>>>(s_raw, t_raw, out);
    max_cls<<<1024, 256>>>(classifier);

    dim3 gemm_grid(CC / 256, NROWS / 128);

    // student GEMM 1 (+ folded tea_img one-hot fill)
    gemm_fp16<2><<<gemm_grid, 256, 2 * TBUF>>>(out + OFF_S, queue,
                                               out + OFF_SI + 1, LDC1, 1.0f / 0.07f,
                                               out + OFF_TI);
    // student GEMM 2 (+ folded tea_text zero fill)
    gemm_fp16<1><<<gemm_grid, 256, 2 * TBUF>>>(out + OFF_S, classifier,
                                               out + OFF_ST, CC, 1.0f / 0.07f,
                                               out + OFF_TT);
    // teacher: int8 screening, top-2 partials only (2x fp16 rate)
    gemm_s8_top2<<<gemm_grid, 256, 2 * S8BUF>>>(out + OFF_T, classifier);

    // exact-fp32 refine: labels + true softmax probs for near-tie rows
    argmax_refine<<<NROWS, 256>>>(out + OFF_T, classifier, out);

    scatter_kernel<<<NROWS, 256>>>(out + OFF_T);
    update_queue<<<(DIMK * CC) / 256, 256>>>(queue, qptr, out + OFF_Q);
    update_ptr<<<CC / 256, 256>>>(qptr, out + OFF_P);
}

// round 11
// speedup vs baseline: 1.2213x; 1.2213x over previous
#include <cuda_runtime.h>
#include <math.h>
#include <stdint.h>

// Problem constants
#define NROWS 4096
#define DIMK  1024
#define CC    16384
#define LDC1  (CC + 1)

// Output layout offsets (floats), tuple order flattened row-major
#define OFF_SI 0ULL                                  // logit_stu_img [N, C+1]
#define OFF_TI (OFF_SI + (size_t)NROWS * LDC1)       // logit_tea_img [N, C+1]
#define OFF_ST (OFF_TI + (size_t)NROWS * LDC1)       // logit_stu_text [N, C]
#define OFF_TT (OFF_ST + (size_t)NROWS * CC)         // logit_tea_text [N, C]
#define OFF_S  (OFF_TT + (size_t)NROWS * CC)         // s [N, DIM]
#define OFF_T  (OFF_S  + (size_t)NROWS * DIMK)       // t [N, DIM]
#define OFF_Q  (OFF_T  + (size_t)NROWS * DIMK)       // new_queue [DIM, C]
#define OFF_P  (OFF_Q  + (size_t)DIMK * CC)          // new_ptr [C]

#define NBLK 64   // teacher GEMM n-tiles (CC/256)
#define MAXC 32   // refine candidate cap

// Scratch (static device globals; no allocation).
// Self-cleaning invariant: g_sums and g_counts are zero at the start of every
// kernel_launch (zero-initialized at load; reset by their last reader each
// run — scatter only writes columns with count>0, and update_queue zeroes
// exactly those columns).
__device__ __align__(16) float g_sums[(size_t)DIMK * CC];   // [DIM][C]
__device__ float g_counts[CC];
__device__ int   g_labels[NROWS];
__device__ float g_pmax[(size_t)NROWS * NBLK * 2];
__device__ int   g_parg[(size_t)NROWS * NBLK * 2];

// ---------------------------------------------------------------------------
// helpers
// ---------------------------------------------------------------------------
__device__ __forceinline__ uint32_t f16x2_pack(float lo, float hi) {
    uint32_t r;
    asm("cvt.rn.f16x2.f32 %0, %1, %2;" : "=r"(r) : "f"(hi), "f"(lo));
    return r;
}

__device__ __forceinline__ void mma16(float* c, const uint4& a, uint32_t b0, uint32_t b1) {
    asm volatile(
        "mma.sync.aligned.m16n8k16.row.col.f32.f16.f16.f32 "
        "{%0,%1,%2,%3}, {%4,%5,%6,%7}, {%8,%9}, {%0,%1,%2,%3};\n"
        : "+f"(c[0]), "+f"(c[1]), "+f"(c[2]), "+f"(c[3])
        : "r"(a.x), "r"(a.y), "r"(a.z), "r"(a.w), "r"(b0), "r"(b1));
}

struct Top2 { float v1, v2; int c1, c2; };
__device__ __forceinline__ void t2_init(Top2& t) {
    t.v1 = -3.4e38f; t.v2 = -3.4e38f; t.c1 = 0x7fffffff; t.c2 = 0x7fffffff;
}
__device__ __forceinline__ void t2_upd(Top2& t, float v, int c) {
    if (v > t.v1 || (v == t.v1 && c < t.c1)) {
        t.v2 = t.v1; t.c2 = t.c1; t.v1 = v; t.c1 = c;
    } else if (v > t.v2 || (v == t.v2 && c < t.c2)) {
        t.v2 = v; t.c2 = c;
    }
}
__device__ __forceinline__ void t2_merge_shfl(Top2& t, int d) {
    float ov1 = __shfl_xor_sync(0xffffffffu, t.v1, d);
    int   oc1 = __shfl_xor_sync(0xffffffffu, t.c1, d);
    float ov2 = __shfl_xor_sync(0xffffffffu, t.v2, d);
    int   oc2 = __shfl_xor_sync(0xffffffffu, t.c2, d);
    t2_upd(t, ov1, oc1);
    t2_upd(t, ov2, oc2);
}

// ---------------------------------------------------------------------------
// Kernel 1: row-normalize s,t; write s,t to out; write positive logit col 0
// ---------------------------------------------------------------------------
__global__ void norm_kernel(const float* __restrict__ sr,
                            const float* __restrict__ tr,
                            float* __restrict__ out) {
    int n = blockIdx.x;
    int tid = threadIdx.x;
    const float4* s4 = (const float4*)(sr + (size_t)n * DIMK);
    const float4* t4 = (const float4*)(tr + (size_t)n * DIMK);
    float4 a = s4[tid];
    float4 b = t4[tid];
    float ss = a.x * a.x + a.y * a.y + a.z * a.z + a.w * a.w;
    float tt = b.x * b.x + b.y * b.y + b.z * b.z + b.w * b.w;
    float st = a.x * b.x + a.y * b.y + a.z * b.z + a.w * b.w;

    __shared__ float r0[256], r1[256], r2[256];
    r0[tid] = ss; r1[tid] = tt; r2[tid] = st;
    __syncthreads();
    #pragma unroll
    for (int s = 128; s > 0; s >>= 1) {
        if (tid < s) { r0[tid] += r0[tid + s]; r1[tid] += r1[tid + s]; r2[tid] += r2[tid + s]; }
        __syncthreads();
    }
    float ns = sqrtf(r0[0]);
    float nt = sqrtf(r1[0]);
    float inv_s = 1.0f / fmaxf(ns, 1e-12f);
    float inv_t = 1.0f / fmaxf(nt, 1e-12f);

    float4 so = make_float4(a.x * inv_s, a.y * inv_s, a.z * inv_s, a.w * inv_s);
    float4 to = make_float4(b.x * inv_t, b.y * inv_t, b.z * inv_t, b.w * inv_t);
    ((float4*)(out + OFF_S + (size_t)n * DIMK))[tid] = so;
    ((float4*)(out + OFF_T + (size_t)n * DIMK))[tid] = to;

    if (tid == 0) {
        float sp = r2[0] * inv_s * inv_t;
        out[OFF_SI + (size_t)n * LDC1] = sp * (1.0f / 0.07f);
    }
}

// ---------------------------------------------------------------------------
// Kernel 2: vectorized zero of a float region (count must be /4)
// ---------------------------------------------------------------------------
__global__ void zero_region(float* __restrict__ p, size_t n4) {
    float4 z = make_float4(0.f, 0.f, 0.f, 0.f);
    float4* q = (float4*)p;
    for (size_t i = (size_t)blockIdx.x * blockDim.x + threadIdx.x; i < n4;
         i += (size_t)gridDim.x * blockDim.x)
        q[i] = z;
}

// Kernel 2b: tea_img col-0 ones (rest already zeroed); exact one-hot
__global__ void ones_tea_img(float* __restrict__ out) {
    int n = blockIdx.x * blockDim.x + threadIdx.x;
    if (n < NROWS) out[OFF_TI + (size_t)n * LDC1] = 1.0f;
}

// ---------------------------------------------------------------------------
// Kernel 4: FP16 mma GEMM, CTA 128x256, warp 64x64, 8 warps, double-buffered.
// fp16 e5m10 has the same 2^-11 unit roundoff as TF32 on these small-range
// operands, at 2x the HMMA rate.
// WRITEC=1: C[m,n] = scale * sum_k A[m,k]*B[k,n] written to Cout.
// WRITEC=0: no C writes; per-row TOP-2 (val,col) partials to g_pmax/g_parg.
// SMEM: stage = A 8KB + B 16KB = 24KB, double buffered (48KB).
// ---------------------------------------------------------------------------
#define TBUF 24576
#define TOB  8192

template<int WRITEC>
__global__ __launch_bounds__(256, 1)
void gemm_fp16(const float* __restrict__ A, const float* __restrict__ B,
               float* __restrict__ Cout, int ldc, float scale) {
    extern __shared__ char smc[];

    const int tid  = threadIdx.x;
    const int lane = tid & 31;
    const int wid  = tid >> 5;
    const int wm   = wid & 1;
    const int wn   = wid >> 1;
    const int mbase = blockIdx.y * 128;
    const int nbase = blockIdx.x * 256;

    // A fill meta: idx -> (m, k4); f16x2 words are k-pairs
    int baseA[4], slA[4], swA[4];
    const float* aptr[4];
    #pragma unroll
    for (int q = 0; q < 4; q++) {
        int idx = tid + 256 * q;
        int m = idx >> 3, k4 = (idx & 7) * 4;
        aptr[q] = A + (size_t)(mbase + m) * DIMK + k4;
        int fm = m >> 4, mr = m & 15, fk = k4 >> 4;
        int r0 = ((mr >> 3) & 1) + ((k4 & 8) ? 2 : 0);
        baseA[q] = (fk * 8 + fm) * 512 + r0 * 4;
        slA[q] = ((mr & 7) * 4 + ((k4 & 7) >> 1)) * 16;
        swA[q] = fk << 4;
    }
    // B fill meta: idx -> (kpair kp, n4); words pack two k-rows at one n
    int baseB[4], slB[4], swB[4];
    const float* bptr[4];
    #pragma unroll
    for (int q = 0; q < 4; q++) {
        int idx = tid + 256 * q;
        int kp = idx >> 6, n4 = (idx & 63) * 4;
        bptr[q] = B + (size_t)(2 * kp) * CC + nbase + n4;
        int fn2 = n4 >> 4, fnb = (n4 >> 3) & 1, fk = kp >> 3;
        baseB[q] = TOB + (fk * 16 + fn2) * 512 + (fnb * 2 + ((kp >> 2) & 1)) * 4;
        slB[q] = ((n4 & 7) * 4 + (kp & 3)) * 16;
        swB[q] = (fn2 & 7) << 4;
    }

    float c[4][8][4];
    #pragma unroll
    for (int i = 0; i < 4; i++)
        #pragma unroll
        for (int j = 0; j < 8; j++)
            #pragma unroll
            for (int r = 0; r < 4; r++) c[i][j][r] = 0.0f;

    const int lane16 = lane * 16;

    float4 ra[4], rb0[4], rb1[4];

    // prologue
    #pragma unroll
    for (int q = 0; q < 4; q++) {
        ra[q]  = *(const float4*)aptr[q];
        rb0[q] = *(const float4*)bptr[q];
        rb1[q] = *(const float4*)(bptr[q] + CC);
    }
    {
        char* buf = smc;
        #pragma unroll
        for (int q = 0; q < 4; q++) {
            *(uint32_t*)(buf + baseA[q] + ((slA[q])      ^ swA[q])) = f16x2_pack(ra[q].x, ra[q].y);
            *(uint32_t*)(buf + baseA[q] + ((slA[q] + 16) ^ swA[q])) = f16x2_pack(ra[q].z, ra[q].w);
            float l0[4] = {rb0[q].x, rb0[q].y, rb0[q].z, rb0[q].w};
            float l1[4] = {rb1[q].x, rb1[q].y, rb1[q].z, rb1[q].w};
            #pragma unroll
            for (int j = 0; j < 4; j++)
                *(uint32_t*)(buf + baseB[q] + ((slB[q] + j * 64) ^ swB[q])) = f16x2_pack(l0[j], l1[j]);
        }
    }
    __syncthreads();

    for (int kt = 0; kt < 32; kt++) {
        char* cur = smc + (kt & 1) * TBUF;
        char* nxt = smc + ((kt & 1) ^ 1) * TBUF;
        if (kt < 31) {
            int kb = (kt + 1) * 32;
            #pragma unroll
            for (int q = 0; q < 4; q++) {
                ra[q]  = *(const float4*)(aptr[q] + kb);
                rb0[q] = *(const float4*)(bptr[q] + (size_t)kb * CC);
                rb1[q] = *(const float4*)(bptr[q] + (size_t)(kb + 1) * CC);
            }
        }
        #pragma unroll
        for (int fk = 0; fk < 2; fk++) {
            uint4 ahf[4], bhf[4];
            #pragma unroll
            for (int i = 0; i < 4; i++) {
                int off = (fk * 8 + wm * 4 + i) * 512 + (lane16 ^ (fk << 4));
                ahf[i] = *(const uint4*)(cur + off);
            }
            #pragma unroll
            for (int j = 0; j < 4; j++) {
                int fn2 = 4 * wn + j;
                int off = TOB + (fk * 16 + fn2) * 512 + (lane16 ^ ((fn2 & 7) << 4));
                bhf[j] = *(const uint4*)(cur + off);
            }
            #pragma unroll
            for (int i = 0; i < 4; i++)
                #pragma unroll
                for (int j = 0; j < 4; j++) {
                    mma16(c[i][2 * j],     ahf[i], bhf[j].x, bhf[j].y);
                    mma16(c[i][2 * j + 1], ahf[i], bhf[j].z, bhf[j].w);
                }
        }
        if (kt < 31) {
            #pragma unroll
            for (int q = 0; q < 4; q++) {
                *(uint32_t*)(nxt + baseA[q] + ((slA[q])      ^ swA[q])) = f16x2_pack(ra[q].x, ra[q].y);
                *(uint32_t*)(nxt + baseA[q] + ((slA[q] + 16) ^ swA[q])) = f16x2_pack(ra[q].z, ra[q].w);
                float l0[4] = {rb0[q].x, rb0[q].y, rb0[q].z, rb0[q].w};
                float l1[4] = {rb1[q].x, rb1[q].y, rb1[q].z, rb1[q].w};
                #pragma unroll
                for (int j = 0; j < 4; j++)
                    *(uint32_t*)(nxt + baseB[q] + ((slB[q] + j * 64) ^ swB[q])) = f16x2_pack(l0[j], l1[j]);
            }
        }
        __syncthreads();
    }

    if (WRITEC) {
        // C frag mapping: rows wm*64 + i*16 + (lane>>2) (+8),
        // cols wn*64 + jn*8 + (lane&3)*2 (+1)
        #pragma unroll
        for (int i = 0; i < 4; i++) {
            int r0 = mbase + wm * 64 + i * 16 + (lane >> 2);
            #pragma unroll
            for (int jn = 0; jn < 8; jn++) {
                int col = nbase + wn * 64 + jn * 8 + (lane & 3) * 2;
                size_t o = (size_t)r0 * ldc + col;
                Cout[o]     = c[i][jn][0] * scale;
                Cout[o + 1] = c[i][jn][1] * scale;
                size_t o2 = o + (size_t)8 * ldc;
                Cout[o2]     = c[i][jn][2] * scale;
                Cout[o2 + 1] = c[i][jn][3] * scale;
            }
        }
    } else {
        // top-2 per row over this 128x256 tile
        float* rv1 = (float*)smc;
        int*   rc1 = (int*)(smc + 2048);
        float* rv2 = (float*)(smc + 4096);
        int*   rc2 = (int*)(smc + 6144);
        #pragma unroll
        for (int i = 0; i < 4; i++) {
            Top2 a, b;
            t2_init(a); t2_init(b);
            #pragma unroll
            for (int jn = 0; jn < 8; jn++) {
                int col = wn * 64 + jn * 8 + (lane & 3) * 2;
                t2_upd(a, c[i][jn][0], col);
                t2_upd(a, c[i][jn][1], col + 1);
                t2_upd(b, c[i][jn][2], col);
                t2_upd(b, c[i][jn][3], col + 1);
            }
            t2_merge_shfl(a, 1); t2_merge_shfl(a, 2);
            t2_merge_shfl(b, 1); t2_merge_shfl(b, 2);
            if ((lane & 3) == 0) {
                int rA = wm * 64 + i * 16 + (lane >> 2);
                rv1[rA * 4 + wn] = a.v1; rc1[rA * 4 + wn] = a.c1;
                rv2[rA * 4 + wn] = a.v2; rc2[rA * 4 + wn] = a.c2;
                int rB = rA + 8;
                rv1[rB * 4 + wn] = b.v1; rc1[rB * 4 + wn] = b.c1;
                rv2[rB * 4 + wn] = b.v2; rc2[rB * 4 + wn] = b.c2;
            }
        }
        __syncthreads();
        if (tid < 128) {
            Top2 t;
            t2_init(t);
            #pragma unroll
            for (int w = 0; w < 4; w++) {
                t2_upd(t, rv1[tid * 4 + w], rc1[tid * 4 + w]);
                t2_upd(t, rv2[tid * 4 + w], rc2[tid * 4 + w]);
            }
            size_t o = ((size_t)(mbase + tid) * NBLK + blockIdx.x) * 2;
            g_pmax[o]     = t.v1;  g_parg[o]     = nbase + t.c1;
            g_pmax[o + 1] = t.v2;  g_parg[o + 1] = nbase + t.c2;
        }
    }
}

// ---------------------------------------------------------------------------
// Kernel 5: candidate refine. fp16 top-2 partials -> threshold max-0.05
// (>100 sigma of fp16 dot error) -> exact fp32 re-dot -> exact argmax + exact
// softmax over survivors (others underflow to exact fp32 zero at TEMP=1e-4).
// ---------------------------------------------------------------------------
__global__ void argmax_refine(const float* __restrict__ t,
                              const float* __restrict__ cls,
                              float* __restrict__ out) {
    int n = blockIdx.x;
    int tid = threadIdx.x;
    __shared__ float pv[NBLK * 2];
    __shared__ int   pi[NBLK * 2];
    for (int i = tid; i < NBLK * 2; i += 256) {
        pv[i] = g_pmax[(size_t)n * NBLK * 2 + i];
        pi[i] = g_parg[(size_t)n * NBLK * 2 + i];
    }
    __syncthreads();
    __shared__ int cand[MAXC];
    __shared__ int ncand_s;
    if (tid == 0) {
        float m = -3.4e38f;
        for (int i = 0; i < NBLK * 2; i++) m = fmaxf(m, pv[i]);
        float thr = m - 0.05f;
        int nc = 0;
        for (int i = 0; i < NBLK * 2 && nc < MAXC; i++)
            if (pv[i] >= thr) cand[nc++] = pi[i];
        ncand_s = nc;
    }
    __syncthreads();
    int nc = ncand_s;

    __shared__ float ev[MAXC];
    __shared__ float red[256];
    const float* trow = t + (size_t)n * DIMK;
    for (int k = 0; k < nc; k++) {
        int col = cand[k];
        float part = 0.0f;
        for (int d = tid; d < DIMK; d += 256)
            part += trow[d] * cls[(size_t)d * CC + col];
        red[tid] = part;
        __syncthreads();
        #pragma unroll
        for (int s = 128; s > 0; s >>= 1) {
            if (tid < s) red[tid] += red[tid + s];
            __syncthreads();
        }
        if (tid == 0) ev[k] = red[0];
        __syncthreads();
    }

    if (tid == 0) {
        float v1 = -3.4e38f;
        int best = 0x7fffffff;
        for (int k = 0; k < nc; k++) {
            if (ev[k] > v1 || (ev[k] == v1 && cand[k] < best)) { v1 = ev[k]; best = cand[k]; }
        }
        g_labels[n] = best;
        float x1 = v1 / 1e-4f;
        float sum = 0.0f;
        for (int k = 0; k < nc; k++)
            sum += expf(ev[k] / 1e-4f - x1);
        float inv = 1.0f / sum;
        for (int k = 0; k < nc; k++)
            out[OFF_TT + (size_t)n * CC + cand[k]] = expf(ev[k] / 1e-4f - x1) * inv;
    }
}

// ---------------------------------------------------------------------------
// Kernel 6: scatter t rows into per-cluster sums/counts
// ---------------------------------------------------------------------------
__global__ void scatter_kernel(const float* __restrict__ t) {
    int n = blockIdx.x;
    int lab = g_labels[n];
    const float* trow = t + (size_t)n * DIMK;
    for (int d = threadIdx.x; d < DIMK; d += 256)
        atomicAdd(&g_sums[(size_t)d * CC + lab], trow[d]);
    if (threadIdx.x == 0)
        atomicAdd(&g_counts[lab], 1.0f);
}

// ---------------------------------------------------------------------------
// Kernel 7: EMA queue update -> new_queue [DIM, C].
// Self-cleaning: resets g_sums for present columns (non-present columns were
// never written by scatter, so they are already zero) — removes the dedicated
// 64MB zero pass AND skips the g_sums read for ~75% of elements.
// ---------------------------------------------------------------------------
__global__ void update_queue(const float* __restrict__ queue,
                             const int* __restrict__ qptr,
                             float* __restrict__ outq) {
    size_t idx = (size_t)blockIdx.x * blockDim.x + threadIdx.x;
    int c = (int)(idx & (CC - 1));
    float cnt = g_counts[c];
    float q = queue[idx];
    if (cnt > 0.0f) {
        float sv = g_sums[idx];
        g_sums[idx] = 0.0f;
        float z = sv / cnt;
        bool init = qptr[c] > 0;
        outq[idx] = init ? (0.99f * q + 0.01f * z) : z;
    } else {
        outq[idx] = q;
    }
}

// ---------------------------------------------------------------------------
// Kernel 8: new_ptr; resets g_counts (self-cleaning)
// ---------------------------------------------------------------------------
__global__ void update_ptr(const int* __restrict__ qptr, float* __restrict__ outp) {
    int c = blockIdx.x * blockDim.x + threadIdx.x;
    if (c < CC) {
        float cnt = g_counts[c];
        outp[c] = (cnt > 0.0f) ? 1.0f : (float)qptr[c];
        g_counts[c] = 0.0f;
    }
}

// ---------------------------------------------------------------------------
extern "C" void kernel_launch(void* const* d_in, const int* in_sizes, int n_in,
                              void* d_out, int out_size) {
    const float* s_raw      = (const float*)d_in[0];
    const float* t_raw      = (const float*)d_in[1];
    const float* queue      = (const float*)d_in[2];
    const float* classifier = (const float*)d_in[3];
    const int*   qptr       = (const int*)d_in[4];
    float* out = (float*)d_out;

    cudaFuncSetAttribute(gemm_fp16<1>,
                         cudaFuncAttributeMaxDynamicSharedMemorySize, 2 * TBUF);
    cudaFuncSetAttribute(gemm_fp16<0>,
                         cudaFuncAttributeMaxDynamicSharedMemorySize, 2 * TBUF);

    norm_kernel<<<NROWS, 256>>>(s_raw, t_raw, out);
    // tea_img: zero region then col-0 ones  (N*LDC1 is divisible by 4)
    zero_region<<<2048, 256>>>(out + OFF_TI, (size_t)NROWS * LDC1 / 4);
    ones_tea_img<<<NROWS / 256, 256>>>(out);
    // tea_text zero (refine writes the few nonzeros)
    zero_region<<<2048, 256>>>(out + OFF_TT, (size_t)NROWS * CC / 4);

    dim3 gemm_grid(CC / 256, NROWS / 128);

    // student GEMMs: single-pass fp16 (2^-11 roundoff, same as TF32; ~3e-4)
    gemm_fp16<1><<<gemm_grid, 256, 2 * TBUF>>>(out + OFF_S, queue,
                                               out + OFF_SI + 1, LDC1, 1.0f / 0.07f);
    gemm_fp16<1><<<gemm_grid, 256, 2 * TBUF>>>(out + OFF_S, classifier,
                                               out + OFF_ST, CC, 1.0f / 0.07f);
    // teacher: single-pass fp16 screening, top-2 partials only
    gemm_fp16<0><<<gemm_grid, 256, 2 * TBUF>>>(out + OFF_T, classifier,
                                               nullptr, 0, 1.0f);

    // exact-fp32 refine: labels + true softmax probs for near-tie rows
    argmax_refine<<<NROWS, 256>>>(out + OFF_T, classifier, out);

    scatter_kernel<<<NROWS, 256>>>(out + OFF_T);
    update_queue<<<(DIMK * CC) / 256, 256>>>(queue, qptr, out + OFF_Q);
    update_ptr<<<CC / 256, 256>>>(qptr, out + OFF_P);
}

// round 12
// speedup vs baseline: 1.2958x; 1.0609x over previous
#include <cuda_runtime.h>
#include <math.h>
#include <stdint.h>

// Problem constants
#define NROWS 4096
#define DIMK  1024
#define CC    16384
#define LDC1  (CC + 1)

// Output layout offsets (floats), tuple order flattened row-major
#define OFF_SI 0ULL                                  // logit_stu_img [N, C+1]
#define OFF_TI (OFF_SI + (size_t)NROWS * LDC1)       // logit_tea_img [N, C+1]
#define OFF_ST (OFF_TI + (size_t)NROWS * LDC1)       // logit_stu_text [N, C]
#define OFF_TT (OFF_ST + (size_t)NROWS * CC)         // logit_tea_text [N, C]
#define OFF_S  (OFF_TT + (size_t)NROWS * CC)         // s [N, DIM]
#define OFF_T  (OFF_S  + (size_t)NROWS * DIMK)       // t [N, DIM]
#define OFF_Q  (OFF_T  + (size_t)NROWS * DIMK)       // new_queue [DIM, C]
#define OFF_P  (OFF_Q  + (size_t)DIMK * CC)          // new_ptr [C]

#define NBLK 64   // teacher GEMM n-tiles (CC/256)
#define MAXC 32   // refine candidate cap

// Scratch (static device globals; no allocation).
// g_sums/g_counts are zero at the start of every kernel_launch:
// zero-initialized at load; update_queue re-zeroes ALL of g_sums each run
// (unconditional coalesced sweep) and update_ptr re-zeroes g_counts.
__device__ __align__(16) float g_sums[(size_t)DIMK * CC];   // [DIM][C]
__device__ float g_counts[CC];
__device__ int   g_labels[NROWS];
__device__ float g_pmax[(size_t)NROWS * NBLK * 2];
__device__ int   g_parg[(size_t)NROWS * NBLK * 2];

// ---------------------------------------------------------------------------
// helpers
// ---------------------------------------------------------------------------
__device__ __forceinline__ uint32_t f16x2_pack(float lo, float hi) {
    uint32_t r;
    asm("cvt.rn.f16x2.f32 %0, %1, %2;" : "=r"(r) : "f"(hi), "f"(lo));
    return r;
}

__device__ __forceinline__ void mma16(float* c, const uint4& a, uint32_t b0, uint32_t b1) {
    asm volatile(
        "mma.sync.aligned.m16n8k16.row.col.f32.f16.f16.f32 "
        "{%0,%1,%2,%3}, {%4,%5,%6,%7}, {%8,%9}, {%0,%1,%2,%3};\n"
        : "+f"(c[0]), "+f"(c[1]), "+f"(c[2]), "+f"(c[3])
        : "r"(a.x), "r"(a.y), "r"(a.z), "r"(a.w), "r"(b0), "r"(b1));
}

struct Top2 { float v1, v2; int c1, c2; };
__device__ __forceinline__ void t2_init(Top2& t) {
    t.v1 = -3.4e38f; t.v2 = -3.4e38f; t.c1 = 0x7fffffff; t.c2 = 0x7fffffff;
}
__device__ __forceinline__ void t2_upd(Top2& t, float v, int c) {
    if (v > t.v1 || (v == t.v1 && c < t.c1)) {
        t.v2 = t.v1; t.c2 = t.c1; t.v1 = v; t.c1 = c;
    } else if (v > t.v2 || (v == t.v2 && c < t.c2)) {
        t.v2 = v; t.c2 = c;
    }
}
__device__ __forceinline__ void t2_merge_shfl(Top2& t, int d) {
    float ov1 = __shfl_xor_sync(0xffffffffu, t.v1, d);
    int   oc1 = __shfl_xor_sync(0xffffffffu, t.c1, d);
    float ov2 = __shfl_xor_sync(0xffffffffu, t.v2, d);
    int   oc2 = __shfl_xor_sync(0xffffffffu, t.c2, d);
    t2_upd(t, ov1, oc1);
    t2_upd(t, ov2, oc2);
}

// ---------------------------------------------------------------------------
// Kernel 1: row-normalize s,t; write s,t to out; write positive logit col 0
// ---------------------------------------------------------------------------
__global__ void norm_kernel(const float* __restrict__ sr,
                            const float* __restrict__ tr,
                            float* __restrict__ out) {
    int n = blockIdx.x;
    int tid = threadIdx.x;
    const float4* s4 = (const float4*)(sr + (size_t)n * DIMK);
    const float4* t4 = (const float4*)(tr + (size_t)n * DIMK);
    float4 a = s4[tid];
    float4 b = t4[tid];
    float ss = a.x * a.x + a.y * a.y + a.z * a.z + a.w * a.w;
    float tt = b.x * b.x + b.y * b.y + b.z * b.z + b.w * b.w;
    float st = a.x * b.x + a.y * b.y + a.z * b.z + a.w * b.w;

    __shared__ float r0[256], r1[256], r2[256];
    r0[tid] = ss; r1[tid] = tt; r2[tid] = st;
    __syncthreads();
    #pragma unroll
    for (int s = 128; s > 0; s >>= 1) {
        if (tid < s) { r0[tid] += r0[tid + s]; r1[tid] += r1[tid + s]; r2[tid] += r2[tid + s]; }
        __syncthreads();
    }
    float ns = sqrtf(r0[0]);
    float nt = sqrtf(r1[0]);
    float inv_s = 1.0f / fmaxf(ns, 1e-12f);
    float inv_t = 1.0f / fmaxf(nt, 1e-12f);

    float4 so = make_float4(a.x * inv_s, a.y * inv_s, a.z * inv_s, a.w * inv_s);
    float4 to = make_float4(b.x * inv_t, b.y * inv_t, b.z * inv_t, b.w * inv_t);
    ((float4*)(out + OFF_S + (size_t)n * DIMK))[tid] = so;
    ((float4*)(out + OFF_T + (size_t)n * DIMK))[tid] = to;

    if (tid == 0) {
        float sp = r2[0] * inv_s * inv_t;
        out[OFF_SI + (size_t)n * LDC1] = sp * (1.0f / 0.07f);
    }
}

// ---------------------------------------------------------------------------
// Kernel 2: vectorized zero of a float region (count must be /4)
// ---------------------------------------------------------------------------
__global__ void zero_region(float* __restrict__ p, size_t n4) {
    float4 z = make_float4(0.f, 0.f, 0.f, 0.f);
    float4* q = (float4*)p;
    for (size_t i = (size_t)blockIdx.x * blockDim.x + threadIdx.x; i < n4;
         i += (size_t)gridDim.x * blockDim.x)
        q[i] = z;
}

// Kernel 2b: tea_img col-0 ones (rest already zeroed); exact one-hot
__global__ void ones_tea_img(float* __restrict__ out) {
    int n = blockIdx.x * blockDim.x + threadIdx.x;
    if (n < NROWS) out[OFF_TI + (size_t)n * LDC1] = 1.0f;
}

// ---------------------------------------------------------------------------
// Kernel 4: FP16 mma GEMM, CTA 128x256, 512 threads (16 warps, warp 32x64).
// 4 warps/SMSP for latency hiding (R10 ncu: tensor 37%, issue 17% at 256thr
// — issue-limited, not tensor-limited). fp16 e5m10 has the same 2^-11 unit
// roundoff as TF32 on these small-range operands.
// WRITEC=1: C[m,n] = scale * sum_k A[m,k]*B[k,n] written to Cout.
// WRITEC=0: no C writes; per-row TOP-2 (val,col) partials to g_pmax/g_parg.
// SMEM: stage = A 8KB + B 16KB = 24KB, double buffered (48KB).
// ---------------------------------------------------------------------------
#define TBUF 24576
#define TOB  8192

template<int WRITEC>
__global__ __launch_bounds__(512, 1)
void gemm_fp16(const float* __restrict__ A, const float* __restrict__ B,
               float* __restrict__ Cout, int ldc, float scale) {
    extern __shared__ char smc[];

    const int tid  = threadIdx.x;
    const int lane = tid & 31;
    const int wid  = tid >> 5;
    const int wm   = wid & 3;    // 4 m-warps x 32 rows
    const int wn   = wid >> 2;   // 4 n-warps x 64 cols
    const int mbase = blockIdx.y * 128;
    const int nbase = blockIdx.x * 256;

    // A fill meta: idx = tid + 512q (q<2): m = idx>>3, k4 = (idx&7)*4
    int baseA[2], slA[2], swA[2];
    const float* aptr[2];
    #pragma unroll
    for (int q = 0; q < 2; q++) {
        int idx = tid + 512 * q;
        int m = idx >> 3, k4 = (idx & 7) * 4;
        aptr[q] = A + (size_t)(mbase + m) * DIMK + k4;
        int fm = m >> 4, mr = m & 15, fk = k4 >> 4;
        int r0 = ((mr >> 3) & 1) + ((k4 & 8) ? 2 : 0);
        baseA[q] = (fk * 8 + fm) * 512 + r0 * 4;
        slA[q] = ((mr & 7) * 4 + ((k4 & 7) >> 1)) * 16;
        swA[q] = fk << 4;
    }
    // B fill meta: idx = tid + 512q (q<2): kp = idx>>6, n4 = (idx&63)*4
    int baseB[2], slB[2], swB[2];
    const float* bptr[2];
    #pragma unroll
    for (int q = 0; q < 2; q++) {
        int idx = tid + 512 * q;
        int kp = idx >> 6, n4 = (idx & 63) * 4;
        bptr[q] = B + (size_t)(2 * kp) * CC + nbase + n4;
        int fn2 = n4 >> 4, fnb = (n4 >> 3) & 1, fk = kp >> 3;
        baseB[q] = TOB + (fk * 16 + fn2) * 512 + (fnb * 2 + ((kp >> 2) & 1)) * 4;
        slB[q] = ((n4 & 7) * 4 + (kp & 3)) * 16;
        swB[q] = (fn2 & 7) << 4;
    }

    float c[2][8][4];
    #pragma unroll
    for (int i = 0; i < 2; i++)
        #pragma unroll
        for (int j = 0; j < 8; j++)
            #pragma unroll
            for (int r = 0; r < 4; r++) c[i][j][r] = 0.0f;

    const int lane16 = lane * 16;

    float4 ra[2], rb0[2], rb1[2];

    // prologue
    #pragma unroll
    for (int q = 0; q < 2; q++) {
        ra[q]  = *(const float4*)aptr[q];
        rb0[q] = *(const float4*)bptr[q];
        rb1[q] = *(const float4*)(bptr[q] + CC);
    }
    {
        char* buf = smc;
        #pragma unroll
        for (int q = 0; q < 2; q++) {
            *(uint32_t*)(buf + baseA[q] + ((slA[q])      ^ swA[q])) = f16x2_pack(ra[q].x, ra[q].y);
            *(uint32_t*)(buf + baseA[q] + ((slA[q] + 16) ^ swA[q])) = f16x2_pack(ra[q].z, ra[q].w);
            float l0[4] = {rb0[q].x, rb0[q].y, rb0[q].z, rb0[q].w};
            float l1[4] = {rb1[q].x, rb1[q].y, rb1[q].z, rb1[q].w};
            #pragma unroll
            for (int j = 0; j < 4; j++)
                *(uint32_t*)(buf + baseB[q] + ((slB[q] + j * 64) ^ swB[q])) = f16x2_pack(l0[j], l1[j]);
        }
    }
    __syncthreads();

    for (int kt = 0; kt < 32; kt++) {
        char* cur = smc + (kt & 1) * TBUF;
        char* nxt = smc + ((kt & 1) ^ 1) * TBUF;
        if (kt < 31) {
            int kb = (kt + 1) * 32;
            #pragma unroll
            for (int q = 0; q < 2; q++) {
                ra[q]  = *(const float4*)(aptr[q] + kb);
                rb0[q] = *(const float4*)(bptr[q] + (size_t)kb * CC);
                rb1[q] = *(const float4*)(bptr[q] + (size_t)(kb + 1) * CC);
            }
        }
        #pragma unroll
        for (int fk = 0; fk < 2; fk++) {
            uint4 ahf[2], bhf[4];
            #pragma unroll
            for (int i = 0; i < 2; i++) {
                int off = (fk * 8 + wm * 2 + i) * 512 + (lane16 ^ (fk << 4));
                ahf[i] = *(const uint4*)(cur + off);
            }
            #pragma unroll
            for (int j = 0; j < 4; j++) {
                int fn2 = 4 * wn + j;
                int off = TOB + (fk * 16 + fn2) * 512 + (lane16 ^ ((fn2 & 7) << 4));
                bhf[j] = *(const uint4*)(cur + off);
            }
            #pragma unroll
            for (int i = 0; i < 2; i++)
                #pragma unroll
                for (int j = 0; j < 4; j++) {
                    mma16(c[i][2 * j],     ahf[i], bhf[j].x, bhf[j].y);
                    mma16(c[i][2 * j + 1], ahf[i], bhf[j].z, bhf[j].w);
                }
        }
        if (kt < 31) {
            #pragma unroll
            for (int q = 0; q < 2; q++) {
                *(uint32_t*)(nxt + baseA[q] + ((slA[q])      ^ swA[q])) = f16x2_pack(ra[q].x, ra[q].y);
                *(uint32_t*)(nxt + baseA[q] + ((slA[q] + 16) ^ swA[q])) = f16x2_pack(ra[q].z, ra[q].w);
                float l0[4] = {rb0[q].x, rb0[q].y, rb0[q].z, rb0[q].w};
                float l1[4] = {rb1[q].x, rb1[q].y, rb1[q].z, rb1[q].w};
                #pragma unroll
                for (int j = 0; j < 4; j++)
                    *(uint32_t*)(nxt + baseB[q] + ((slB[q] + j * 64) ^ swB[q])) = f16x2_pack(l0[j], l1[j]);
            }
        }
        __syncthreads();
    }

    if (WRITEC) {
        // C frag mapping: rows wm*32 + i*16 + (lane>>2) (+8),
        // cols wn*64 + jn*8 + (lane&3)*2 (+1)
        #pragma unroll
        for (int i = 0; i < 2; i++) {
            int r0 = mbase + wm * 32 + i * 16 + (lane >> 2);
            #pragma unroll
            for (int jn = 0; jn < 8; jn++) {
                int col = nbase + wn * 64 + jn * 8 + (lane & 3) * 2;
                size_t o = (size_t)r0 * ldc + col;
                Cout[o]     = c[i][jn][0] * scale;
                Cout[o + 1] = c[i][jn][1] * scale;
                size_t o2 = o + (size_t)8 * ldc;
                Cout[o2]     = c[i][jn][2] * scale;
                Cout[o2 + 1] = c[i][jn][3] * scale;
            }
        }
    } else {
        // top-2 per row over this 128x256 tile
        float* rv1 = (float*)smc;
        int*   rc1 = (int*)(smc + 2048);
        float* rv2 = (float*)(smc + 4096);
        int*   rc2 = (int*)(smc + 6144);
        #pragma unroll
        for (int i = 0; i < 2; i++) {
            Top2 a, b;
            t2_init(a); t2_init(b);
            #pragma unroll
            for (int jn = 0; jn < 8; jn++) {
                int col = wn * 64 + jn * 8 + (lane & 3) * 2;
                t2_upd(a, c[i][jn][0], col);
                t2_upd(a, c[i][jn][1], col + 1);
                t2_upd(b, c[i][jn][2], col);
                t2_upd(b, c[i][jn][3], col + 1);
            }
            t2_merge_shfl(a, 1); t2_merge_shfl(a, 2);
            t2_merge_shfl(b, 1); t2_merge_shfl(b, 2);
            if ((lane & 3) == 0) {
                int rA = wm * 32 + i * 16 + (lane >> 2);
                rv1[rA * 4 + wn] = a.v1; rc1[rA * 4 + wn] = a.c1;
                rv2[rA * 4 + wn] = a.v2; rc2[rA * 4 + wn] = a.c2;
                int rB = rA + 8;
                rv1[rB * 4 + wn] = b.v1; rc1[rB * 4 + wn] = b.c1;
                rv2[rB * 4 + wn] = b.v2; rc2[rB * 4 + wn] = b.c2;
            }
        }
        __syncthreads();
        if (tid < 128) {
            Top2 t;
            t2_init(t);
            #pragma unroll
            for (int w = 0; w < 4; w++) {
                t2_upd(t, rv1[tid * 4 + w], rc1[tid * 4 + w]);
                t2_upd(t, rv2[tid * 4 + w], rc2[tid * 4 + w]);
            }
            size_t o = ((size_t)(mbase + tid) * NBLK + blockIdx.x) * 2;
            g_pmax[o]     = t.v1;  g_parg[o]     = nbase + t.c1;
            g_pmax[o + 1] = t.v2;  g_parg[o + 1] = nbase + t.c2;
        }
    }
}

// ---------------------------------------------------------------------------
// Kernel 5: candidate refine. fp16 top-2 partials -> threshold max-0.05
// (>100 sigma of fp16 dot error) -> exact fp32 re-dot -> exact argmax + exact
// softmax over survivors (others underflow to exact fp32 zero at TEMP=1e-4).
// ---------------------------------------------------------------------------
__global__ void argmax_refine(const float* __restrict__ t,
                              const float* __restrict__ cls,
                              float* __restrict__ out) {
    int n = blockIdx.x;
    int tid = threadIdx.x;
    __shared__ float pv[NBLK * 2];
    __shared__ int   pi[NBLK * 2];
    for (int i = tid; i < NBLK * 2; i += 256) {
        pv[i] = g_pmax[(size_t)n * NBLK * 2 + i];
        pi[i] = g_parg[(size_t)n * NBLK * 2 + i];
    }
    __syncthreads();
    __shared__ int cand[MAXC];
    __shared__ int ncand_s;
    if (tid == 0) {
        float m = -3.4e38f;
        for (int i = 0; i < NBLK * 2; i++) m = fmaxf(m, pv[i]);
        float thr = m - 0.05f;
        int nc = 0;
        for (int i = 0; i < NBLK * 2 && nc < MAXC; i++)
            if (pv[i] >= thr) cand[nc++] = pi[i];
        ncand_s = nc;
    }
    __syncthreads();
    int nc = ncand_s;

    __shared__ float ev[MAXC];
    __shared__ float red[256];
    const float* trow = t + (size_t)n * DIMK;
    for (int k = 0; k < nc; k++) {
        int col = cand[k];
        float part = 0.0f;
        for (int d = tid; d < DIMK; d += 256)
            part += trow[d] * cls[(size_t)d * CC + col];
        red[tid] = part;
        __syncthreads();
        #pragma unroll
        for (int s = 128; s > 0; s >>= 1) {
            if (tid < s) red[tid] += red[tid + s];
            __syncthreads();
        }
        if (tid == 0) ev[k] = red[0];
        __syncthreads();
    }

    if (tid == 0) {
        float v1 = -3.4e38f;
        int best = 0x7fffffff;
        for (int k = 0; k < nc; k++) {
            if (ev[k] > v1 || (ev[k] == v1 && cand[k] < best)) { v1 = ev[k]; best = cand[k]; }
        }
        g_labels[n] = best;
        float x1 = v1 / 1e-4f;
        float sum = 0.0f;
        for (int k = 0; k < nc; k++)
            sum += expf(ev[k] / 1e-4f - x1);
        float inv = 1.0f / sum;
        for (int k = 0; k < nc; k++)
            out[OFF_TT + (size_t)n * CC + cand[k]] = expf(ev[k] / 1e-4f - x1) * inv;
    }
}

// ---------------------------------------------------------------------------
// Kernel 6: scatter t rows into per-cluster sums/counts
// ---------------------------------------------------------------------------
__global__ void scatter_kernel(const float* __restrict__ t) {
    int n = blockIdx.x;
    int lab = g_labels[n];
    const float* trow = t + (size_t)n * DIMK;
    for (int d = threadIdx.x; d < DIMK; d += 256)
        atomicAdd(&g_sums[(size_t)d * CC + lab], trow[d]);
    if (threadIdx.x == 0)
        atomicAdd(&g_counts[lab], 1.0f);
}

// ---------------------------------------------------------------------------
// Kernel 7: EMA queue update -> new_queue [DIM, C].
// Unconditionally reads and re-zeroes g_sums (fully coalesced sweep) — folds
// the old zero_scratch pass into this kernel at identical traffic.
// ---------------------------------------------------------------------------
__global__ void update_queue(const float* __restrict__ queue,
                             const int* __restrict__ qptr,
                             float* __restrict__ outq) {
    size_t idx = (size_t)blockIdx.x * blockDim.x + threadIdx.x;
    int c = (int)(idx & (CC - 1));
    float cnt = g_counts[c];
    float q = queue[idx];
    float sv = g_sums[idx];
    g_sums[idx] = 0.0f;
    float z = sv / fmaxf(cnt, 1.0f);
    bool present = cnt > 0.0f;
    bool init = qptr[c] > 0;
    float ema = 0.99f * q + 0.01f * z;
    float ncol = init ? ema : z;
    outq[idx] = present ? ncol : q;
}

// ---------------------------------------------------------------------------
// Kernel 8: new_ptr; resets g_counts (self-cleaning)
// ---------------------------------------------------------------------------
__global__ void update_ptr(const int* __restrict__ qptr, float* __restrict__ outp) {
    int c = blockIdx.x * blockDim.x + threadIdx.x;
    if (c < CC) {
        float cnt = g_counts[c];
        outp[c] = (cnt > 0.0f) ? 1.0f : (float)qptr[c];
        g_counts[c] = 0.0f;
    }
}

// ---------------------------------------------------------------------------
extern "C" void kernel_launch(void* const* d_in, const int* in_sizes, int n_in,
                              void* d_out, int out_size) {
    const float* s_raw      = (const float*)d_in[0];
    const float* t_raw      = (const float*)d_in[1];
    const float* queue      = (const float*)d_in[2];
    const float* classifier = (const float*)d_in[3];
    const int*   qptr       = (const int*)d_in[4];
    float* out = (float*)d_out;

    cudaFuncSetAttribute(gemm_fp16<1>,
                         cudaFuncAttributeMaxDynamicSharedMemorySize, 2 * TBUF);
    cudaFuncSetAttribute(gemm_fp16<0>,
                         cudaFuncAttributeMaxDynamicSharedMemorySize, 2 * TBUF);

    norm_kernel<<<NROWS, 256>>>(s_raw, t_raw, out);
    // tea_img: zero region then col-0 ones  (N*LDC1 is divisible by 4)
    zero_region<<<2048, 256>>>(out + OFF_TI, (size_t)NROWS * LDC1 / 4);
    ones_tea_img<<<NROWS / 256, 256>>>(out);
    // tea_text zero (refine writes the few nonzeros)
    zero_region<<<2048, 256>>>(out + OFF_TT, (size_t)NROWS * CC / 4);

    dim3 gemm_grid(CC / 256, NROWS / 128);

    // student GEMMs: single-pass fp16 (2^-11 roundoff, same as TF32; ~3e-4)
    gemm_fp16<1><<<gemm_grid, 512, 2 * TBUF>>>(out + OFF_S, queue,
                                               out + OFF_SI + 1, LDC1, 1.0f / 0.07f);
    gemm_fp16<1><<<gemm_grid, 512, 2 * TBUF>>>(out + OFF_S, classifier,
                                               out + OFF_ST, CC, 1.0f / 0.07f);
    // teacher: single-pass fp16 screening, top-2 partials only
    gemm_fp16<0><<<gemm_grid, 512, 2 * TBUF>>>(out + OFF_T, classifier,
                                               nullptr, 0, 1.0f);

    // exact-fp32 refine: labels + true softmax probs for near-tie rows
    argmax_refine<<<NROWS, 256>>>(out + OFF_T, classifier, out);

    scatter_kernel<<<NROWS, 256>>>(out + OFF_T);
    update_queue<<<(DIMK * CC) / 256, 256>>>(queue, qptr, out + OFF_Q);
    update_ptr<<<CC / 256, 256>>>(qptr, out + OFF_P);
}

// round 13
// speedup vs baseline: 1.4520x; 1.1205x over previous
#include <cuda_runtime.h>
#include <math.h>
#include <stdint.h>

// Problem constants
#define NROWS 4096
#define DIMK  1024
#define CC    16384
#define LDC1  (CC + 1)

// Output layout offsets (floats), tuple order flattened row-major
#define OFF_SI 0ULL                                  // logit_stu_img [N, C+1]
#define OFF_TI (OFF_SI + (size_t)NROWS * LDC1)       // logit_tea_img [N, C+1]
#define OFF_ST (OFF_TI + (size_t)NROWS * LDC1)       // logit_stu_text [N, C]
#define OFF_TT (OFF_ST + (size_t)NROWS * CC)         // logit_tea_text [N, C]
#define OFF_S  (OFF_TT + (size_t)NROWS * CC)         // s [N, DIM]
#define OFF_T  (OFF_S  + (size_t)NROWS * DIMK)       // t [N, DIM]
#define OFF_Q  (OFF_T  + (size_t)NROWS * DIMK)       // new_queue [DIM, C]
#define OFF_P  (OFF_Q  + (size_t)DIMK * CC)          // new_ptr [C]

#define NBLK 64   // teacher GEMM n-tiles (CC/256)
#define MAXC 32   // refine candidate cap

// Scratch (static device globals; no allocation).
// g_sums/g_counts are zero at the start of every kernel_launch:
// zero-initialized at load; update_queue re-zeroes the present columns of
// g_sums each run (non-present were never written), update_ptr re-zeroes
// g_counts.
__device__ __align__(16) float g_sums[(size_t)DIMK * CC];   // [DIM][C]
__device__ float g_counts[CC];
__device__ int   g_labels[NROWS];
__device__ float g_pmax[(size_t)NROWS * NBLK * 2];
__device__ int   g_parg[(size_t)NROWS * NBLK * 2];

// ---------------------------------------------------------------------------
// helpers
// ---------------------------------------------------------------------------
__device__ __forceinline__ uint32_t f16x2_pack(float lo, float hi) {
    uint32_t r;
    asm("cvt.rn.f16x2.f32 %0, %1, %2;" : "=r"(r) : "f"(hi), "f"(lo));
    return r;
}

__device__ __forceinline__ void mma16(float* c, const uint4& a, uint32_t b0, uint32_t b1) {
    asm volatile(
        "mma.sync.aligned.m16n8k16.row.col.f32.f16.f16.f32 "
        "{%0,%1,%2,%3}, {%4,%5,%6,%7}, {%8,%9}, {%0,%1,%2,%3};\n"
        : "+f"(c[0]), "+f"(c[1]), "+f"(c[2]), "+f"(c[3])
        : "r"(a.x), "r"(a.y), "r"(a.z), "r"(a.w), "r"(b0), "r"(b1));
}

struct Top2 { float v1, v2; int c1, c2; };
__device__ __forceinline__ void t2_init(Top2& t) {
    t.v1 = -3.4e38f; t.v2 = -3.4e38f; t.c1 = 0x7fffffff; t.c2 = 0x7fffffff;
}
__device__ __forceinline__ void t2_upd(Top2& t, float v, int c) {
    if (v > t.v1 || (v == t.v1 && c < t.c1)) {
        t.v2 = t.v1; t.c2 = t.c1; t.v1 = v; t.c1 = c;
    } else if (v > t.v2 || (v == t.v2 && c < t.c2)) {
        t.v2 = v; t.c2 = c;
    }
}
__device__ __forceinline__ void t2_merge_shfl(Top2& t, int d) {
    float ov1 = __shfl_xor_sync(0xffffffffu, t.v1, d);
    int   oc1 = __shfl_xor_sync(0xffffffffu, t.c1, d);
    float ov2 = __shfl_xor_sync(0xffffffffu, t.v2, d);
    int   oc2 = __shfl_xor_sync(0xffffffffu, t.c2, d);
    t2_upd(t, ov1, oc1);
    t2_upd(t, ov2, oc2);
}

// ---------------------------------------------------------------------------
// Kernel 1: row-normalize s,t; write s,t to out; write positive logit col 0
// ---------------------------------------------------------------------------
__global__ void norm_kernel(const float* __restrict__ sr,
                            const float* __restrict__ tr,
                            float* __restrict__ out) {
    int n = blockIdx.x;
    int tid = threadIdx.x;
    const float4* s4 = (const float4*)(sr + (size_t)n * DIMK);
    const float4* t4 = (const float4*)(tr + (size_t)n * DIMK);
    float4 a = s4[tid];
    float4 b = t4[tid];
    float ss = a.x * a.x + a.y * a.y + a.z * a.z + a.w * a.w;
    float tt = b.x * b.x + b.y * b.y + b.z * b.z + b.w * b.w;
    float st = a.x * b.x + a.y * b.y + a.z * b.z + a.w * b.w;

    __shared__ float r0[256], r1[256], r2[256];
    r0[tid] = ss; r1[tid] = tt; r2[tid] = st;
    __syncthreads();
    #pragma unroll
    for (int s = 128; s > 0; s >>= 1) {
        if (tid < s) { r0[tid] += r0[tid + s]; r1[tid] += r1[tid + s]; r2[tid] += r2[tid + s]; }
        __syncthreads();
    }
    float ns = sqrtf(r0[0]);
    float nt = sqrtf(r1[0]);
    float inv_s = 1.0f / fmaxf(ns, 1e-12f);
    float inv_t = 1.0f / fmaxf(nt, 1e-12f);

    float4 so = make_float4(a.x * inv_s, a.y * inv_s, a.z * inv_s, a.w * inv_s);
    float4 to = make_float4(b.x * inv_t, b.y * inv_t, b.z * inv_t, b.w * inv_t);
    ((float4*)(out + OFF_S + (size_t)n * DIMK))[tid] = so;
    ((float4*)(out + OFF_T + (size_t)n * DIMK))[tid] = to;

    if (tid == 0) {
        float sp = r2[0] * inv_s * inv_t;
        out[OFF_SI + (size_t)n * LDC1] = sp * (1.0f / 0.07f);
    }
}

// ---------------------------------------------------------------------------
// Kernel 2: fused output fills.
// Region 1 (tea_img [N, LDC1]): exact one-hot at col 0 (TEMP=1e-4 underflow).
// Region 2 (tea_text [N, CC]): zeros (refine writes the few nonzeros).
// ---------------------------------------------------------------------------
__global__ void fill_outputs(float* __restrict__ out) {
    size_t gtid = (size_t)blockIdx.x * blockDim.x + threadIdx.x;
    const size_t gstride = (size_t)gridDim.x * blockDim.x;

    // tea_img one-hot: float4 stores over N*LDC1 (divisible by 4)
    {
        size_t total4 = (size_t)NROWS * LDC1 / 4;
        unsigned int m = (unsigned int)((4 * gtid) % LDC1);
        const unsigned int inc = (unsigned int)((4 * gstride) % LDC1);
        float4* base = (float4*)(out + OFF_TI);
        for (size_t i = gtid; i < total4; i += gstride) {
            float4 v = make_float4(0.f, 0.f, 0.f, 0.f);
            unsigned int j = (m == 0) ? 0u : (unsigned int)LDC1 - m;
            if (j < 4) (&v.x)[j] = 1.0f;
            base[i] = v;
            m += inc; if (m >= (unsigned int)LDC1) m -= (unsigned int)LDC1;
        }
    }
    // tea_text zero
    {
        size_t total4 = (size_t)NROWS * CC / 4;
        float4 z = make_float4(0.f, 0.f, 0.f, 0.f);
        float4* base = (float4*)(out + OFF_TT);
        for (size_t i = gtid; i < total4; i += gstride)
            base[i] = z;
    }
}

// ---------------------------------------------------------------------------
// Kernel 4: FP16 mma GEMM, CTA 128x256, 512 threads (16 warps, warp 32x64).
// 4 warps/SMSP for latency hiding. fp16 e5m10 has the same 2^-11 unit
// roundoff as TF32 on these small-range operands, at 2x the HMMA rate.
// WRITEC=1: C[m,n] = scale * sum_k A[m,k]*B[k,n] written to Cout.
// WRITEC=0: no C writes; per-row TOP-2 (val,col) partials to g_pmax/g_parg.
// SMEM: stage = A 8KB + B 16KB = 24KB, double buffered (48KB).
// ---------------------------------------------------------------------------
#define TBUF 24576
#define TOB  8192

template<int WRITEC>
__global__ __launch_bounds__(512, 1)
void gemm_fp16(const float* __restrict__ A, const float* __restrict__ B,
               float* __restrict__ Cout, int ldc, float scale) {
    extern __shared__ char smc[];

    const int tid  = threadIdx.x;
    const int lane = tid & 31;
    const int wid  = tid >> 5;
    const int wm   = wid & 3;    // 4 m-warps x 32 rows
    const int wn   = wid >> 2;   // 4 n-warps x 64 cols
    const int mbase = blockIdx.y * 128;
    const int nbase = blockIdx.x * 256;

    // A fill meta: idx = tid + 512q (q<2): m = idx>>3, k4 = (idx&7)*4
    int baseA[2], slA[2], swA[2];
    const float* aptr[2];
    #pragma unroll
    for (int q = 0; q < 2; q++) {
        int idx = tid + 512 * q;
        int m = idx >> 3, k4 = (idx & 7) * 4;
        aptr[q] = A + (size_t)(mbase + m) * DIMK + k4;
        int fm = m >> 4, mr = m & 15, fk = k4 >> 4;
        int r0 = ((mr >> 3) & 1) + ((k4 & 8) ? 2 : 0);
        baseA[q] = (fk * 8 + fm) * 512 + r0 * 4;
        slA[q] = ((mr & 7) * 4 + ((k4 & 7) >> 1)) * 16;
        swA[q] = fk << 4;
    }
    // B fill meta: idx = tid + 512q (q<2): kp = idx>>6, n4 = (idx&63)*4
    int baseB[2], slB[2], swB[2];
    const float* bptr[2];
    #pragma unroll
    for (int q = 0; q < 2; q++) {
        int idx = tid + 512 * q;
        int kp = idx >> 6, n4 = (idx & 63) * 4;
        bptr[q] = B + (size_t)(2 * kp) * CC + nbase + n4;
        int fn2 = n4 >> 4, fnb = (n4 >> 3) & 1, fk = kp >> 3;
        baseB[q] = TOB + (fk * 16 + fn2) * 512 + (fnb * 2 + ((kp >> 2) & 1)) * 4;
        slB[q] = ((n4 & 7) * 4 + (kp & 3)) * 16;
        swB[q] = (fn2 & 7) << 4;
    }

    float c[2][8][4];
    #pragma unroll
    for (int i = 0; i < 2; i++)
        #pragma unroll
        for (int j = 0; j < 8; j++)
            #pragma unroll
            for (int r = 0; r < 4; r++) c[i][j][r] = 0.0f;

    const int lane16 = lane * 16;

    float4 ra[2], rb0[2], rb1[2];

    // prologue
    #pragma unroll
    for (int q = 0; q < 2; q++) {
        ra[q]  = *(const float4*)aptr[q];
        rb0[q] = *(const float4*)bptr[q];
        rb1[q] = *(const float4*)(bptr[q] + CC);
    }
    {
        char* buf = smc;
        #pragma unroll
        for (int q = 0; q < 2; q++) {
            *(uint32_t*)(buf + baseA[q] + ((slA[q])      ^ swA[q])) = f16x2_pack(ra[q].x, ra[q].y);
            *(uint32_t*)(buf + baseA[q] + ((slA[q] + 16) ^ swA[q])) = f16x2_pack(ra[q].z, ra[q].w);
            float l0[4] = {rb0[q].x, rb0[q].y, rb0[q].z, rb0[q].w};
            float l1[4] = {rb1[q].x, rb1[q].y, rb1[q].z, rb1[q].w};
            #pragma unroll
            for (int j = 0; j < 4; j++)
                *(uint32_t*)(buf + baseB[q] + ((slB[q] + j * 64) ^ swB[q])) = f16x2_pack(l0[j], l1[j]);
        }
    }
    __syncthreads();

    for (int kt = 0; kt < 32; kt++) {
        char* cur = smc + (kt & 1) * TBUF;
        char* nxt = smc + ((kt & 1) ^ 1) * TBUF;
        if (kt < 31) {
            int kb = (kt + 1) * 32;
            #pragma unroll
            for (int q = 0; q < 2; q++) {
                ra[q]  = *(const float4*)(aptr[q] + kb);
                rb0[q] = *(const float4*)(bptr[q] + (size_t)kb * CC);
                rb1[q] = *(const float4*)(bptr[q] + (size_t)(kb + 1) * CC);
            }
        }
        #pragma unroll
        for (int fk = 0; fk < 2; fk++) {
            uint4 ahf[2], bhf[4];
            #pragma unroll
            for (int i = 0; i < 2; i++) {
                int off = (fk * 8 + wm * 2 + i) * 512 + (lane16 ^ (fk << 4));
                ahf[i] = *(const uint4*)(cur + off);
            }
            #pragma unroll
            for (int j = 0; j < 4; j++) {
                int fn2 = 4 * wn + j;
                int off = TOB + (fk * 16 + fn2) * 512 + (lane16 ^ ((fn2 & 7) << 4));
                bhf[j] = *(const uint4*)(cur + off);
            }
            #pragma unroll
            for (int i = 0; i < 2; i++)
                #pragma unroll
                for (int j = 0; j < 4; j++) {
                    mma16(c[i][2 * j],     ahf[i], bhf[j].x, bhf[j].y);
                    mma16(c[i][2 * j + 1], ahf[i], bhf[j].z, bhf[j].w);
                }
        }
        if (kt < 31) {
            #pragma unroll
            for (int q = 0; q < 2; q++) {
                *(uint32_t*)(nxt + baseA[q] + ((slA[q])      ^ swA[q])) = f16x2_pack(ra[q].x, ra[q].y);
                *(uint32_t*)(nxt + baseA[q] + ((slA[q] + 16) ^ swA[q])) = f16x2_pack(ra[q].z, ra[q].w);
                float l0[4] = {rb0[q].x, rb0[q].y, rb0[q].z, rb0[q].w};
                float l1[4] = {rb1[q].x, rb1[q].y, rb1[q].z, rb1[q].w};
                #pragma unroll
                for (int j = 0; j < 4; j++)
                    *(uint32_t*)(nxt + baseB[q] + ((slB[q] + j * 64) ^ swB[q])) = f16x2_pack(l0[j], l1[j]);
            }
        }
        __syncthreads();
    }

    if (WRITEC) {
        // C frag mapping: rows wm*32 + i*16 + (lane>>2) (+8),
        // cols wn*64 + jn*8 + (lane&3)*2 (+1)
        #pragma unroll
        for (int i = 0; i < 2; i++) {
            int r0 = mbase + wm * 32 + i * 16 + (lane >> 2);
            #pragma unroll
            for (int jn = 0; jn < 8; jn++) {
                int col = nbase + wn * 64 + jn * 8 + (lane & 3) * 2;
                size_t o = (size_t)r0 * ldc + col;
                Cout[o]     = c[i][jn][0] * scale;
                Cout[o + 1] = c[i][jn][1] * scale;
                size_t o2 = o + (size_t)8 * ldc;
                Cout[o2]     = c[i][jn][2] * scale;
                Cout[o2 + 1] = c[i][jn][3] * scale;
            }
        }
    } else {
        // top-2 per row over this 128x256 tile
        float* rv1 = (float*)smc;
        int*   rc1 = (int*)(smc + 2048);
        float* rv2 = (float*)(smc + 4096);
        int*   rc2 = (int*)(smc + 6144);
        #pragma unroll
        for (int i = 0; i < 2; i++) {
            Top2 a, b;
            t2_init(a); t2_init(b);
            #pragma unroll
            for (int jn = 0; jn < 8; jn++) {
                int col = wn * 64 + jn * 8 + (lane & 3) * 2;
                t2_upd(a, c[i][jn][0], col);
                t2_upd(a, c[i][jn][1], col + 1);
                t2_upd(b, c[i][jn][2], col);
                t2_upd(b, c[i][jn][3], col + 1);
            }
            t2_merge_shfl(a, 1); t2_merge_shfl(a, 2);
            t2_merge_shfl(b, 1); t2_merge_shfl(b, 2);
            if ((lane & 3) == 0) {
                int rA = wm * 32 + i * 16 + (lane >> 2);
                rv1[rA * 4 + wn] = a.v1; rc1[rA * 4 + wn] = a.c1;
                rv2[rA * 4 + wn] = a.v2; rc2[rA * 4 + wn] = a.c2;
                int rB = rA + 8;
                rv1[rB * 4 + wn] = b.v1; rc1[rB * 4 + wn] = b.c1;
                rv2[rB * 4 + wn] = b.v2; rc2[rB * 4 + wn] = b.c2;
            }
        }
        __syncthreads();
        if (tid < 128) {
            Top2 t;
            t2_init(t);
            #pragma unroll
            for (int w = 0; w < 4; w++) {
                t2_upd(t, rv1[tid * 4 + w], rc1[tid * 4 + w]);
                t2_upd(t, rv2[tid * 4 + w], rc2[tid * 4 + w]);
            }
            size_t o = ((size_t)(mbase + tid) * NBLK + blockIdx.x) * 2;
            g_pmax[o]     = t.v1;  g_parg[o]     = nbase + t.c1;
            g_pmax[o + 1] = t.v2;  g_parg[o + 1] = nbase + t.c2;
        }
    }
}

// ---------------------------------------------------------------------------
// Kernel 5: candidate refine. fp16 top-2 partials -> threshold max-0.05
// (>100 sigma of fp16 dot error) -> exact fp32 re-dot -> exact argmax + exact
// softmax over survivors (others underflow to exact fp32 zero at TEMP=1e-4).
// ---------------------------------------------------------------------------
__global__ void argmax_refine(const float* __restrict__ t,
                              const float* __restrict__ cls,
                              float* __restrict__ out) {
    int n = blockIdx.x;
    int tid = threadIdx.x;
    __shared__ float pv[NBLK * 2];
    __shared__ int   pi[NBLK * 2];
    for (int i = tid; i < NBLK * 2; i += 256) {
        pv[i] = g_pmax[(size_t)n * NBLK * 2 + i];
        pi[i] = g_parg[(size_t)n * NBLK * 2 + i];
    }
    __syncthreads();
    __shared__ int cand[MAXC];
    __shared__ int ncand_s;
    if (tid == 0) {
        float m = -3.4e38f;
        for (int i = 0; i < NBLK * 2; i++) m = fmaxf(m, pv[i]);
        float thr = m - 0.05f;
        int nc = 0;
        for (int i = 0; i < NBLK * 2 && nc < MAXC; i++)
            if (pv[i] >= thr) cand[nc++] = pi[i];
        ncand_s = nc;
    }
    __syncthreads();
    int nc = ncand_s;

    __shared__ float ev[MAXC];
    __shared__ float red[256];
    const float* trow = t + (size_t)n * DIMK;
    for (int k = 0; k < nc; k++) {
        int col = cand[k];
        float part = 0.0f;
        for (int d = tid; d < DIMK; d += 256)
            part += trow[d] * cls[(size_t)d * CC + col];
        red[tid] = part;
        __syncthreads();
        #pragma unroll
        for (int s = 128; s > 0; s >>= 1) {
            if (tid < s) red[tid] += red[tid + s];
            __syncthreads();
        }
        if (tid == 0) ev[k] = red[0];
        __syncthreads();
    }

    if (tid == 0) {
        float v1 = -3.4e38f;
        int best = 0x7fffffff;
        for (int k = 0; k < nc; k++) {
            if (ev[k] > v1 || (ev[k] == v1 && cand[k] < best)) { v1 = ev[k]; best = cand[k]; }
        }
        g_labels[n] = best;
        float x1 = v1 / 1e-4f;
        float sum = 0.0f;
        for (int k = 0; k < nc; k++)
            sum += expf(ev[k] / 1e-4f - x1);
        float inv = 1.0f / sum;
        for (int k = 0; k < nc; k++)
            out[OFF_TT + (size_t)n * CC + cand[k]] = expf(ev[k] / 1e-4f - x1) * inv;
    }
}

// ---------------------------------------------------------------------------
// Kernel 6: scatter t rows into per-cluster sums/counts
// ---------------------------------------------------------------------------
__global__ void scatter_kernel(const float* __restrict__ t) {
    int n = blockIdx.x;
    int lab = g_labels[n];
    const float* trow = t + (size_t)n * DIMK;
    for (int d = threadIdx.x; d < DIMK; d += 256)
        atomicAdd(&g_sums[(size_t)d * CC + lab], trow[d]);
    if (threadIdx.x == 0)
        atomicAdd(&g_counts[lab], 1.0f);
}

// ---------------------------------------------------------------------------
// Kernel 7: EMA queue update -> new_queue [DIM, C].
// Reads g_sums unconditionally (coalesced); re-zeroes only present columns
// (non-present were never written by scatter, so they are already zero).
// ---------------------------------------------------------------------------
__global__ void update_queue(const float* __restrict__ queue,
                             const int* __restrict__ qptr,
                             float* __restrict__ outq) {
    size_t idx = (size_t)blockIdx.x * blockDim.x + threadIdx.x;
    int c = (int)(idx & (CC - 1));
    float cnt = g_counts[c];
    float q = queue[idx];
    float sv = g_sums[idx];
    bool present = cnt > 0.0f;
    if (present) g_sums[idx] = 0.0f;
    float z = sv / fmaxf(cnt, 1.0f);
    bool init = qptr[c] > 0;
    float ema = 0.99f * q + 0.01f * z;
    float ncol = init ? ema : z;
    outq[idx] = present ? ncol : q;
}

// ---------------------------------------------------------------------------
// Kernel 8: new_ptr; resets g_counts (self-cleaning)
// ---------------------------------------------------------------------------
__global__ void update_ptr(const int* __restrict__ qptr, float* __restrict__ outp) {
    int c = blockIdx.x * blockDim.x + threadIdx.x;
    if (c < CC) {
        float cnt = g_counts[c];
        outp[c] = (cnt > 0.0f) ? 1.0f : (float)qptr[c];
        g_counts[c] = 0.0f;
    }
}

// ---------------------------------------------------------------------------
extern "C" void kernel_launch(void* const* d_in, const int* in_sizes, int n_in,
                              void* d_out, int out_size) {
    const float* s_raw      = (const float*)d_in[0];
    const float* t_raw      = (const float*)d_in[1];
    const float* queue      = (const float*)d_in[2];
    const float* classifier = (const float*)d_in[3];
    const int*   qptr       = (const int*)d_in[4];
    float* out = (float*)d_out;

    cudaFuncSetAttribute(gemm_fp16<1>,
                         cudaFuncAttributeMaxDynamicSharedMemorySize, 2 * TBUF);
    cudaFuncSetAttribute(gemm_fp16<0>,
                         cudaFuncAttributeMaxDynamicSharedMemorySize, 2 * TBUF);

    norm_kernel<<<NROWS, 256>>>(s_raw, t_raw, out);
    // tea_img one-hot + tea_text zero in one pass
    fill_outputs<<<2048, 256>>>(out);

    dim3 gemm_grid(CC / 256, NROWS / 128);

    // student GEMMs: single-pass fp16 (2^-11 roundoff, same as TF32; ~3e-4)
    gemm_fp16<1><<<gemm_grid, 512, 2 * TBUF>>>(out + OFF_S, queue,
                                               out + OFF_SI + 1, LDC1, 1.0f / 0.07f);
    gemm_fp16<1><<<gemm_grid, 512, 2 * TBUF>>>(out + OFF_S, classifier,
                                               out + OFF_ST, CC, 1.0f / 0.07f);
    // teacher: single-pass fp16 screening, top-2 partials only
    gemm_fp16<0><<<gemm_grid, 512, 2 * TBUF>>>(out + OFF_T, classifier,
                                               nullptr, 0, 1.0f);

    // exact-fp32 refine: labels + true softmax probs for near-tie rows
    argmax_refine<<<NROWS, 256>>>(out + OFF_T, classifier, out);

    scatter_kernel<<<NROWS, 256>>>(out + OFF_T);
    update_queue<<<(DIMK * CC) / 256, 256>>>(queue, qptr, out + OFF_Q);
    update_ptr<<<CC / 256, 256>>>(qptr, out + OFF_P);
}

// round 14
// speedup vs baseline: 1.5496x; 1.0673x over previous
#include <cuda_runtime.h>
#include <math.h>
#include <stdint.h>

// Problem constants
#define NROWS 4096
#define DIMK  1024
#define NKP   512            // DIMK/2 k-pair words
#define CC    16384
#define LDC1  (CC + 1)

// Output layout offsets (floats), tuple order flattened row-major
#define OFF_SI 0ULL                                  // logit_stu_img [N, C+1]
#define OFF_TI (OFF_SI + (size_t)NROWS * LDC1)       // logit_tea_img [N, C+1]
#define OFF_ST (OFF_TI + (size_t)NROWS * LDC1)       // logit_stu_text [N, C]
#define OFF_TT (OFF_ST + (size_t)NROWS * CC)         // logit_tea_text [N, C]
#define OFF_S  (OFF_TT + (size_t)NROWS * CC)         // s [N, DIM]
#define OFF_T  (OFF_S  + (size_t)NROWS * DIMK)       // t [N, DIM]
#define OFF_Q  (OFF_T  + (size_t)NROWS * DIMK)       // new_queue [DIM, C]
#define OFF_P  (OFF_Q  + (size_t)DIMK * CC)          // new_ptr [C]

#define NBLK 64   // teacher GEMM n-tiles (CC/256)
#define MAXC 32   // refine candidate cap

// Scratch (static device globals; no allocation).
// g_sums/g_counts zero at start of every launch (load-zeroed; last readers
// re-zero what was written each run).
__device__ __align__(16) float g_sums[(size_t)DIMK * CC];   // [DIM][C]
__device__ float g_counts[CC];
__device__ int   g_labels[NROWS];
__device__ float g_pmax[(size_t)NROWS * NBLK * 2];
__device__ int   g_parg[(size_t)NROWS * NBLK * 2];
// fp16 operands in GEMM-ready word layout
__device__ __align__(16) uint32_t g_s16[(size_t)NROWS * NKP];  // [m][kp]
__device__ __align__(16) uint32_t g_t16[(size_t)NROWS * NKP];
__device__ __align__(16) uint32_t g_q16[(size_t)NKP * CC];     // [kp][n]
__device__ __align__(16) uint32_t g_c16[(size_t)NKP * CC];

// ---------------------------------------------------------------------------
// helpers
// ---------------------------------------------------------------------------
__device__ __forceinline__ uint32_t f16x2_pack(float lo, float hi) {
    uint32_t r;
    asm("cvt.rn.f16x2.f32 %0, %1, %2;" : "=r"(r) : "f"(hi), "f"(lo));
    return r;
}

__device__ __forceinline__ void mma16(float* c, const uint4& a, uint32_t b0, uint32_t b1) {
    asm volatile(
        "mma.sync.aligned.m16n8k16.row.col.f32.f16.f16.f32 "
        "{%0,%1,%2,%3}, {%4,%5,%6,%7}, {%8,%9}, {%0,%1,%2,%3};\n"
        : "+f"(c[0]), "+f"(c[1]), "+f"(c[2]), "+f"(c[3])
        : "r"(a.x), "r"(a.y), "r"(a.z), "r"(a.w), "r"(b0), "r"(b1));
}

struct Top2 { float v1, v2; int c1, c2; };
__device__ __forceinline__ void t2_init(Top2& t) {
    t.v1 = -3.4e38f; t.v2 = -3.4e38f; t.c1 = 0x7fffffff; t.c2 = 0x7fffffff;
}
__device__ __forceinline__ void t2_upd(Top2& t, float v, int c) {
    if (v > t.v1 || (v == t.v1 && c < t.c1)) {
        t.v2 = t.v1; t.c2 = t.c1; t.v1 = v; t.c1 = c;
    } else if (v > t.v2 || (v == t.v2 && c < t.c2)) {
        t.v2 = v; t.c2 = c;
    }
}
__device__ __forceinline__ void t2_merge_shfl(Top2& t, int d) {
    float ov1 = __shfl_xor_sync(0xffffffffu, t.v1, d);
    int   oc1 = __shfl_xor_sync(0xffffffffu, t.c1, d);
    float ov2 = __shfl_xor_sync(0xffffffffu, t.v2, d);
    int   oc2 = __shfl_xor_sync(0xffffffffu, t.c2, d);
    t2_upd(t, ov1, oc1);
    t2_upd(t, ov2, oc2);
}

// ---------------------------------------------------------------------------
// Kernel 1: row-normalize s,t; write s,t (fp32 out) + s16/t16 (k-pair words);
// positive logit col 0.
// ---------------------------------------------------------------------------
__global__ void norm_kernel(const float* __restrict__ sr,
                            const float* __restrict__ tr,
                            float* __restrict__ out) {
    int n = blockIdx.x;
    int tid = threadIdx.x;
    const float4* s4 = (const float4*)(sr + (size_t)n * DIMK);
    const float4* t4 = (const float4*)(tr + (size_t)n * DIMK);
    float4 a = s4[tid];
    float4 b = t4[tid];
    float ss = a.x * a.x + a.y * a.y + a.z * a.z + a.w * a.w;
    float tt = b.x * b.x + b.y * b.y + b.z * b.z + b.w * b.w;
    float st = a.x * b.x + a.y * b.y + a.z * b.z + a.w * b.w;

    __shared__ float r0[256], r1[256], r2[256];
    r0[tid] = ss; r1[tid] = tt; r2[tid] = st;
    __syncthreads();
    #pragma unroll
    for (int s = 128; s > 0; s >>= 1) {
        if (tid < s) { r0[tid] += r0[tid + s]; r1[tid] += r1[tid + s]; r2[tid] += r2[tid + s]; }
        __syncthreads();
    }
    float ns = sqrtf(r0[0]);
    float nt = sqrtf(r1[0]);
    float inv_s = 1.0f / fmaxf(ns, 1e-12f);
    float inv_t = 1.0f / fmaxf(nt, 1e-12f);

    float4 so = make_float4(a.x * inv_s, a.y * inv_s, a.z * inv_s, a.w * inv_s);
    float4 to = make_float4(b.x * inv_t, b.y * inv_t, b.z * inv_t, b.w * inv_t);
    ((float4*)(out + OFF_S + (size_t)n * DIMK))[tid] = so;
    ((float4*)(out + OFF_T + (size_t)n * DIMK))[tid] = to;

    // fp16 k-pair words (low half = even k) for the GEMMs
    uint2 ws = make_uint2(f16x2_pack(so.x, so.y), f16x2_pack(so.z, so.w));
    uint2 wt = make_uint2(f16x2_pack(to.x, to.y), f16x2_pack(to.z, to.w));
    ((uint2*)(g_s16 + (size_t)n * NKP))[tid] = ws;
    ((uint2*)(g_t16 + (size_t)n * NKP))[tid] = wt;

    if (tid == 0) {
        float sp = r2[0] * inv_s * inv_t;
        out[OFF_SI + (size_t)n * LDC1] = sp * (1.0f / 0.07f);
    }
}

// ---------------------------------------------------------------------------
// Kernel 1b: convert B matrix [DIMK][CC] fp32 -> k-pair-interleaved fp16
// words dst[kp][n] = pack(src[2kp][n], src[2kp+1][n]).  Coalesced.
// ---------------------------------------------------------------------------
__global__ void conv_pair(const float* __restrict__ src, uint32_t* __restrict__ dst) {
    size_t total = (size_t)NKP * (CC / 4);
    for (size_t idx = (size_t)blockIdx.x * blockDim.x + threadIdx.x; idx < total;
         idx += (size_t)gridDim.x * blockDim.x) {
        int kp = (int)(idx >> 12);          // CC/4 = 4096 = 2^12
        int n  = (int)(idx & 4095) * 4;
        float4 s0 = *(const float4*)(src + (size_t)(2 * kp) * CC + n);
        float4 s1 = *(const float4*)(src + (size_t)(2 * kp + 1) * CC + n);
        uint4 w;
        w.x = f16x2_pack(s0.x, s1.x);
        w.y = f16x2_pack(s0.y, s1.y);
        w.z = f16x2_pack(s0.z, s1.z);
        w.w = f16x2_pack(s0.w, s1.w);
        *(uint4*)(dst + (size_t)kp * CC + n) = w;
    }
}

// ---------------------------------------------------------------------------
// Kernel 2: fused output fills (tea_img one-hot, tea_text zeros)
// ---------------------------------------------------------------------------
__global__ void fill_outputs(float* __restrict__ out) {
    size_t gtid = (size_t)blockIdx.x * blockDim.x + threadIdx.x;
    const size_t gstride = (size_t)gridDim.x * blockDim.x;

    {
        size_t total4 = (size_t)NROWS * LDC1 / 4;
        unsigned int m = (unsigned int)((4 * gtid) % LDC1);
        const unsigned int inc = (unsigned int)((4 * gstride) % LDC1);
        float4* base = (float4*)(out + OFF_TI);
        for (size_t i = gtid; i < total4; i += gstride) {
            float4 v = make_float4(0.f, 0.f, 0.f, 0.f);
            unsigned int j = (m == 0) ? 0u : (unsigned int)LDC1 - m;
            if (j < 4) (&v.x)[j] = 1.0f;
            base[i] = v;
            m += inc; if (m >= (unsigned int)LDC1) m -= (unsigned int)LDC1;
        }
    }
    {
        size_t total4 = (size_t)NROWS * CC / 4;
        float4 z = make_float4(0.f, 0.f, 0.f, 0.f);
        float4* base = (float4*)(out + OFF_TT);
        for (size_t i = gtid; i < total4; i += gstride)
            base[i] = z;
    }
}

// ---------------------------------------------------------------------------
// Kernel 4: FP16 mma GEMM, CTA 128x256, 512 threads (16 warps, warp 32x64).
// Operands pre-converted to fp16 word layout: A16 [m][kp] (k-pair words),
// B16 [kp][n] (k-pair-interleaved). Fill is pure LDG.128 + STS.32 (zero ALU):
// A 1 LDG + 4 STS, B 2 LDG + 8 STS per thread per 32-k chunk.
// Compute side identical to the validated R13 kernel.
// WRITEC=1: C = scale * A*B. WRITEC=0: per-row TOP-2 partials only.
// SMEM: stage = A 8KB + B 16KB = 24KB, double buffered (48KB).
// ---------------------------------------------------------------------------
#define TBUF 24576
#define TOB  8192

template<int WRITEC>
__global__ __launch_bounds__(512, 1)
void gemm_fp16(const uint32_t* __restrict__ A16, const uint32_t* __restrict__ B16,
               float* __restrict__ Cout, int ldc, float scale) {
    extern __shared__ char smc[];

    const int tid  = threadIdx.x;
    const int lane = tid & 31;
    const int wid  = tid >> 5;
    const int wm   = wid & 3;    // 4 m-warps x 32 rows
    const int wn   = wid >> 2;   // 4 n-warps x 64 cols
    const int mbase = blockIdx.y * 128;
    const int nbase = blockIdx.x * 256;

    // --- A fill meta: tid -> m (0..127), kpb in {0,4,8,12} ---
    const int am  = tid >> 2;
    const int kpb = (tid & 3) * 4;
    const uint32_t* aptr = A16 + (size_t)(mbase + am) * NKP + kpb;
    const int afm = am >> 4, amr = am & 15;
    const int afk = kpb >> 3;
    const int baseA = (afk * 8 + afm) * 512 + ((amr >> 3) + 2 * ((kpb >> 2) & 1)) * 4;
    const int slA16 = (amr & 7) * 4 * 16;    // + j*16
    const int swA = afk << 4;

    // --- B fill meta: tid -> kpl (0..15), n8 = (tid&31)*8 ---
    const int kpl = tid >> 5;
    const int n8  = (tid & 31) * 8;
    const uint32_t* bptr = B16 + (size_t)kpl * CC + nbase + n8;
    const int bfn2 = n8 >> 4;
    const int bfk  = kpl >> 3;
    const int posB = ((n8 >> 3) & 1) * 2 + ((kpl >> 2) & 1);
    const int baseB = TOB + (bfk * 16 + bfn2) * 512 + posB * 4;
    const int slB16 = (kpl & 3) * 16;        // + e*64
    const int swB = (bfn2 & 7) << 4;

    float c[2][8][4];
    #pragma unroll
    for (int i = 0; i < 2; i++)
        #pragma unroll
        for (int j = 0; j < 8; j++)
            #pragma unroll
            for (int r = 0; r < 4; r++) c[i][j][r] = 0.0f;

    const int lane16 = lane * 16;

    uint4 wa, wb0, wb1;

    // prologue: chunk 0 -> buffer 0
    wa  = *(const uint4*)aptr;
    wb0 = *(const uint4*)bptr;
    wb1 = *(const uint4*)(bptr + 4);
    {
        char* buf = smc;
        *(uint32_t*)(buf + baseA + ((slA16     ) ^ swA)) = wa.x;
        *(uint32_t*)(buf + baseA + ((slA16 + 16) ^ swA)) = wa.y;
        *(uint32_t*)(buf + baseA + ((slA16 + 32) ^ swA)) = wa.z;
        *(uint32_t*)(buf + baseA + ((slA16 + 48) ^ swA)) = wa.w;
        *(uint32_t*)(buf + baseB + ((slB16      ) ^ swB)) = wb0.x;
        *(uint32_t*)(buf + baseB + ((slB16 +  64) ^ swB)) = wb0.y;
        *(uint32_t*)(buf + baseB + ((slB16 + 128) ^ swB)) = wb0.z;
        *(uint32_t*)(buf + baseB + ((slB16 + 192) ^ swB)) = wb0.w;
        *(uint32_t*)(buf + baseB + ((slB16 + 256) ^ swB)) = wb1.x;
        *(uint32_t*)(buf + baseB + ((slB16 + 320) ^ swB)) = wb1.y;
        *(uint32_t*)(buf + baseB + ((slB16 + 384) ^ swB)) = wb1.z;
        *(uint32_t*)(buf + baseB + ((slB16 + 448) ^ swB)) = wb1.w;
    }
    __syncthreads();

    for (int kt = 0; kt < 32; kt++) {
        char* cur = smc + (kt & 1) * TBUF;
        char* nxt = smc + ((kt & 1) ^ 1) * TBUF;
        if (kt < 31) {
            size_t ko = (size_t)(kt + 1) * 16;
            wa  = *(const uint4*)(aptr + ko);
            wb0 = *(const uint4*)(bptr + ko * CC);
            wb1 = *(const uint4*)(bptr + ko * CC + 4);
        }
        #pragma unroll
        for (int fk = 0; fk < 2; fk++) {
            uint4 ahf[2], bhf[4];
            #pragma unroll
            for (int i = 0; i < 2; i++) {
                int off = (fk * 8 + wm * 2 + i) * 512 + (lane16 ^ (fk << 4));
                ahf[i] = *(const uint4*)(cur + off);
            }
            #pragma unroll
            for (int j = 0; j < 4; j++) {
                int fn2 = 4 * wn + j;
                int off = TOB + (fk * 16 + fn2) * 512 + (lane16 ^ ((fn2 & 7) << 4));
                bhf[j] = *(const uint4*)(cur + off);
            }
            #pragma unroll
            for (int i = 0; i < 2; i++)
                #pragma unroll
                for (int j = 0; j < 4; j++) {
                    mma16(c[i][2 * j],     ahf[i], bhf[j].x, bhf[j].y);
                    mma16(c[i][2 * j + 1], ahf[i], bhf[j].z, bhf[j].w);
                }
        }
        if (kt < 31) {
            *(uint32_t*)(nxt + baseA + ((slA16     ) ^ swA)) = wa.x;
            *(uint32_t*)(nxt + baseA + ((slA16 + 16) ^ swA)) = wa.y;
            *(uint32_t*)(nxt + baseA + ((slA16 + 32) ^ swA)) = wa.z;
            *(uint32_t*)(nxt + baseA + ((slA16 + 48) ^ swA)) = wa.w;
            *(uint32_t*)(nxt + baseB + ((slB16      ) ^ swB)) = wb0.x;
            *(uint32_t*)(nxt + baseB + ((slB16 +  64) ^ swB)) = wb0.y;
            *(uint32_t*)(nxt + baseB + ((slB16 + 128) ^ swB)) = wb0.z;
            *(uint32_t*)(nxt + baseB + ((slB16 + 192) ^ swB)) = wb0.w;
            *(uint32_t*)(nxt + baseB + ((slB16 + 256) ^ swB)) = wb1.x;
            *(uint32_t*)(nxt + baseB + ((slB16 + 320) ^ swB)) = wb1.y;
            *(uint32_t*)(nxt + baseB + ((slB16 + 384) ^ swB)) = wb1.z;
            *(uint32_t*)(nxt + baseB + ((slB16 + 448) ^ swB)) = wb1.w;
        }
        __syncthreads();
    }

    if (WRITEC) {
        // C frag mapping: rows wm*32 + i*16 + (lane>>2) (+8),
        // cols wn*64 + jn*8 + (lane&3)*2 (+1)
        #pragma unroll
        for (int i = 0; i < 2; i++) {
            int r0 = mbase + wm * 32 + i * 16 + (lane >> 2);
            #pragma unroll
            for (int jn = 0; jn < 8; jn++) {
                int col = nbase + wn * 64 + jn * 8 + (lane & 3) * 2;
                size_t o = (size_t)r0 * ldc + col;
                Cout[o]     = c[i][jn][0] * scale;
                Cout[o + 1] = c[i][jn][1] * scale;
                size_t o2 = o + (size_t)8 * ldc;
                Cout[o2]     = c[i][jn][2] * scale;
                Cout[o2 + 1] = c[i][jn][3] * scale;
            }
        }
    } else {
        // top-2 per row over this 128x256 tile
        float* rv1 = (float*)smc;
        int*   rc1 = (int*)(smc + 2048);
        float* rv2 = (float*)(smc + 4096);
        int*   rc2 = (int*)(smc + 6144);
        #pragma unroll
        for (int i = 0; i < 2; i++) {
            Top2 a, b;
            t2_init(a); t2_init(b);
            #pragma unroll
            for (int jn = 0; jn < 8; jn++) {
                int col = wn * 64 + jn * 8 + (lane & 3) * 2;
                t2_upd(a, c[i][jn][0], col);
                t2_upd(a, c[i][jn][1], col + 1);
                t2_upd(b, c[i][jn][2], col);
                t2_upd(b, c[i][jn][3], col + 1);
            }
            t2_merge_shfl(a, 1); t2_merge_shfl(a, 2);
            t2_merge_shfl(b, 1); t2_merge_shfl(b, 2);
            if ((lane & 3) == 0) {
                int rA = wm * 32 + i * 16 + (lane >> 2);
                rv1[rA * 4 + wn] = a.v1; rc1[rA * 4 + wn] = a.c1;
                rv2[rA * 4 + wn] = a.v2; rc2[rA * 4 + wn] = a.c2;
                int rB = rA + 8;
                rv1[rB * 4 + wn] = b.v1; rc1[rB * 4 + wn] = b.c1;
                rv2[rB * 4 + wn] = b.v2; rc2[rB * 4 + wn] = b.c2;
            }
        }
        __syncthreads();
        if (tid < 128) {
            Top2 t;
            t2_init(t);
            #pragma unroll
            for (int w = 0; w < 4; w++) {
                t2_upd(t, rv1[tid * 4 + w], rc1[tid * 4 + w]);
                t2_upd(t, rv2[tid * 4 + w], rc2[tid * 4 + w]);
            }
            size_t o = ((size_t)(mbase + tid) * NBLK + blockIdx.x) * 2;
            g_pmax[o]     = t.v1;  g_parg[o]     = nbase + t.c1;
            g_pmax[o + 1] = t.v2;  g_parg[o + 1] = nbase + t.c2;
        }
    }
}

// ---------------------------------------------------------------------------
// Kernel 5: candidate refine. fp16 top-2 partials -> threshold max-0.05
// (>100 sigma of fp16 dot error) -> exact fp32 re-dot -> exact argmax + exact
// softmax over survivors (others underflow to exact fp32 zero at TEMP=1e-4).
// ---------------------------------------------------------------------------
__global__ void argmax_refine(const float* __restrict__ t,
                              const float* __restrict__ cls,
                              float* __restrict__ out) {
    int n = blockIdx.x;
    int tid = threadIdx.x;
    __shared__ float pv[NBLK * 2];
    __shared__ int   pi[NBLK * 2];
    for (int i = tid; i < NBLK * 2; i += 256) {
        pv[i] = g_pmax[(size_t)n * NBLK * 2 + i];
        pi[i] = g_parg[(size_t)n * NBLK * 2 + i];
    }
    __syncthreads();
    __shared__ int cand[MAXC];
    __shared__ int ncand_s;
    if (tid == 0) {
        float m = -3.4e38f;
        for (int i = 0; i < NBLK * 2; i++) m = fmaxf(m, pv[i]);
        float thr = m - 0.05f;
        int nc = 0;
        for (int i = 0; i < NBLK * 2 && nc < MAXC; i++)
            if (pv[i] >= thr) cand[nc++] = pi[i];
        ncand_s = nc;
    }
    __syncthreads();
    int nc = ncand_s;

    __shared__ float ev[MAXC];
    __shared__ float red[256];
    const float* trow = t + (size_t)n * DIMK;
    for (int k = 0; k < nc; k++) {
        int col = cand[k];
        float part = 0.0f;
        for (int d = tid; d < DIMK; d += 256)
            part += trow[d] * cls[(size_t)d * CC + col];
        red[tid] = part;
        __syncthreads();
        #pragma unroll
        for (int s = 128; s > 0; s >>= 1) {
            if (tid < s) red[tid] += red[tid + s];
            __syncthreads();
        }
        if (tid == 0) ev[k] = red[0];
        __syncthreads();
    }

    if (tid == 0) {
        float v1 = -3.4e38f;
        int best = 0x7fffffff;
        for (int k = 0; k < nc; k++) {
            if (ev[k] > v1 || (ev[k] == v1 && cand[k] < best)) { v1 = ev[k]; best = cand[k]; }
        }
        g_labels[n] = best;
        float x1 = v1 / 1e-4f;
        float sum = 0.0f;
        for (int k = 0; k < nc; k++)
            sum += expf(ev[k] / 1e-4f - x1);
        float inv = 1.0f / sum;
        for (int k = 0; k < nc; k++)
            out[OFF_TT + (size_t)n * CC + cand[k]] = expf(ev[k] / 1e-4f - x1) * inv;
    }
}

// ---------------------------------------------------------------------------
// Kernel 6: scatter t rows into per-cluster sums/counts
// ---------------------------------------------------------------------------
__global__ void scatter_kernel(const float* __restrict__ t) {
    int n = blockIdx.x;
    int lab = g_labels[n];
    const float* trow = t + (size_t)n * DIMK;
    for (int d = threadIdx.x; d < DIMK; d += 256)
        atomicAdd(&g_sums[(size_t)d * CC + lab], trow[d]);
    if (threadIdx.x == 0)
        atomicAdd(&g_counts[lab], 1.0f);
}

// ---------------------------------------------------------------------------
// Kernel 7: EMA queue update -> new_queue [DIM, C].
// Reads g_sums unconditionally (coalesced); re-zeroes only present columns
// (non-present were never written by scatter, so they are already zero).
// ---------------------------------------------------------------------------
__global__ void update_queue(const float* __restrict__ queue,
                             const int* __restrict__ qptr,
                             float* __restrict__ outq) {
    size_t idx = (size_t)blockIdx.x * blockDim.x + threadIdx.x;
    int c = (int)(idx & (CC - 1));
    float cnt = g_counts[c];
    float q = queue[idx];
    float sv = g_sums[idx];
    bool present = cnt > 0.0f;
    if (present) g_sums[idx] = 0.0f;
    float z = sv / fmaxf(cnt, 1.0f);
    bool init = qptr[c] > 0;
    float ema = 0.99f * q + 0.01f * z;
    float ncol = init ? ema : z;
    outq[idx] = present ? ncol : q;
}

// ---------------------------------------------------------------------------
// Kernel 8: new_ptr; resets g_counts (self-cleaning)
// ---------------------------------------------------------------------------
__global__ void update_ptr(const int* __restrict__ qptr, float* __restrict__ outp) {
    int c = blockIdx.x * blockDim.x + threadIdx.x;
    if (c < CC) {
        float cnt = g_counts[c];
        outp[c] = (cnt > 0.0f) ? 1.0f : (float)qptr[c];
        g_counts[c] = 0.0f;
    }
}

// ---------------------------------------------------------------------------
extern "C" void kernel_launch(void* const* d_in, const int* in_sizes, int n_in,
                              void* d_out, int out_size) {
    const float* s_raw      = (const float*)d_in[0];
    const float* t_raw      = (const float*)d_in[1];
    const float* queue      = (const float*)d_in[2];
    const float* classifier = (const float*)d_in[3];
    const int*   qptr       = (const int*)d_in[4];
    float* out = (float*)d_out;

    cudaFuncSetAttribute(gemm_fp16<1>,
                         cudaFuncAttributeMaxDynamicSharedMemorySize, 2 * TBUF);
    cudaFuncSetAttribute(gemm_fp16<0>,
                         cudaFuncAttributeMaxDynamicSharedMemorySize, 2 * TBUF);

    uint32_t* dq16;  cudaGetSymbolAddress((void**)&dq16, g_q16);
    uint32_t* dc16;  cudaGetSymbolAddress((void**)&dc16, g_c16);
    uint32_t* ds16;  cudaGetSymbolAddress((void**)&ds16, g_s16);
    uint32_t* dt16;  cudaGetSymbolAddress((void**)&dt16, g_t16);

    norm_kernel<<<NROWS, 256>>>(s_raw, t_raw, out);
    conv_pair<<<4096, 256>>>(queue, dq16);
    conv_pair<<<4096, 256>>>(classifier, dc16);
    fill_outputs<<<2048, 256>>>(out);

    dim3 gemm_grid(CC / 256, NROWS / 128);

    // student GEMMs: single-pass fp16 (2^-11 roundoff, same as TF32; ~3e-4)
    gemm_fp16<1><<<gemm_grid, 512, 2 * TBUF>>>(ds16, dq16,
                                               out + OFF_SI + 1, LDC1, 1.0f / 0.07f);
    gemm_fp16<1><<<gemm_grid, 512, 2 * TBUF>>>(ds16, dc16,
                                               out + OFF_ST, CC, 1.0f / 0.07f);
    // teacher: single-pass fp16 screening, top-2 partials only
    gemm_fp16<0><<<gemm_grid, 512, 2 * TBUF>>>(dt16, dc16,
                                               nullptr, 0, 1.0f);

    // exact-fp32 refine: labels + true softmax probs for near-tie rows
    argmax_refine<<<NROWS, 256>>>(out + OFF_T, classifier, out);

    scatter_kernel<<<NROWS, 256>>>(out + OFF_T);
    update_queue<<<(DIMK * CC) / 256, 256>>>(queue, qptr, out + OFF_Q);
    update_ptr<<<CC / 256, 256>>>(qptr, out + OFF_P);
}

// round 15
// speedup vs baseline: 1.6029x; 1.0344x over previous
#include <cuda_runtime.h>
#include <math.h>
#include <stdint.h>

// Problem constants
#define NROWS 4096
#define DIMK  1024
#define NKP   512            // DIMK/2 k-pair words
#define CC    16384
#define LDC1  (CC + 1)

// Output layout offsets (floats), tuple order flattened row-major
#define OFF_SI 0ULL                                  // logit_stu_img [N, C+1]
#define OFF_TI (OFF_SI + (size_t)NROWS * LDC1)       // logit_tea_img [N, C+1]
#define OFF_ST (OFF_TI + (size_t)NROWS * LDC1)       // logit_stu_text [N, C]
#define OFF_TT (OFF_ST + (size_t)NROWS * CC)         // logit_tea_text [N, C]
#define OFF_S  (OFF_TT + (size_t)NROWS * CC)         // s [N, DIM]
#define OFF_T  (OFF_S  + (size_t)NROWS * DIMK)       // t [N, DIM]
#define OFF_Q  (OFF_T  + (size_t)NROWS * DIMK)       // new_queue [DIM, C]
#define OFF_P  (OFF_Q  + (size_t)DIMK * CC)          // new_ptr [C]

#define NBLK 64   // teacher GEMM n-tiles (CC/256)
#define MAXC 32   // refine candidate cap

// B image geometry: per n-panel (256 cols) per 32-k chunk, one 16KB stage
// image with the swizzle pre-applied (byte-exact copy of the GEMM's B smem).
#define BIMG_CHUNK_BYTES 16384
#define BIMG_PANEL_BYTES ((size_t)32 * BIMG_CHUNK_BYTES)

// Scratch (static device globals; no allocation).
__device__ __align__(16) float g_sums[(size_t)DIMK * CC];   // [DIM][C]
__device__ float g_counts[CC];
__device__ int   g_labels[NROWS];
__device__ float g_pmax[(size_t)NROWS * NBLK * 2];
__device__ int   g_parg[(size_t)NROWS * NBLK * 2];
// fp16 operands
__device__ __align__(16) uint32_t g_s16[(size_t)NROWS * NKP];   // [m][kp]
__device__ __align__(16) uint32_t g_t16[(size_t)NROWS * NKP];
__device__ __align__(16) char g_qimg[(size_t)NBLK * BIMG_PANEL_BYTES];  // 32MB
__device__ __align__(16) char g_cimg[(size_t)NBLK * BIMG_PANEL_BYTES];

// ---------------------------------------------------------------------------
// helpers
// ---------------------------------------------------------------------------
__device__ __forceinline__ uint32_t f16x2_pack(float lo, float hi) {
    uint32_t r;
    asm("cvt.rn.f16x2.f32 %0, %1, %2;" : "=r"(r) : "f"(hi), "f"(lo));
    return r;
}
__device__ __forceinline__ uint32_t smem_u32(const void* p) {
    uint32_t a;
    asm("{ .reg .u64 t; cvta.to.shared.u64 t, %1; cvt.u32.u64 %0, t; }"
        : "=r"(a) : "l"(p));
    return a;
}
__device__ __forceinline__ void cp16(uint32_t sm, const void* g) {
    asm volatile("cp.async.cg.shared.global [%0], [%1], 16;" :: "r"(sm), "l"(g) : "memory");
}
#define CP_COMMIT() asm volatile("cp.async.commit_group;" ::: "memory")
#define CP_WAIT0()  asm volatile("cp.async.wait_group 0;" ::: "memory")

__device__ __forceinline__ void mma16(float* c, const uint4& a, uint32_t b0, uint32_t b1) {
    asm volatile(
        "mma.sync.aligned.m16n8k16.row.col.f32.f16.f16.f32 "
        "{%0,%1,%2,%3}, {%4,%5,%6,%7}, {%8,%9}, {%0,%1,%2,%3};\n"
        : "+f"(c[0]), "+f"(c[1]), "+f"(c[2]), "+f"(c[3])
        : "r"(a.x), "r"(a.y), "r"(a.z), "r"(a.w), "r"(b0), "r"(b1));
}

struct Top2 { float v1, v2; int c1, c2; };
__device__ __forceinline__ void t2_init(Top2& t) {
    t.v1 = -3.4e38f; t.v2 = -3.4e38f; t.c1 = 0x7fffffff; t.c2 = 0x7fffffff;
}
__device__ __forceinline__ void t2_upd(Top2& t, float v, int c) {
    if (v > t.v1 || (v == t.v1 && c < t.c1)) {
        t.v2 = t.v1; t.c2 = t.c1; t.v1 = v; t.c1 = c;
    } else if (v > t.v2 || (v == t.v2 && c < t.c2)) {
        t.v2 = v; t.c2 = c;
    }
}
__device__ __forceinline__ void t2_merge_shfl(Top2& t, int d) {
    float ov1 = __shfl_xor_sync(0xffffffffu, t.v1, d);
    int   oc1 = __shfl_xor_sync(0xffffffffu, t.c1, d);
    float ov2 = __shfl_xor_sync(0xffffffffu, t.v2, d);
    int   oc2 = __shfl_xor_sync(0xffffffffu, t.c2, d);
    t2_upd(t, ov1, oc1);
    t2_upd(t, ov2, oc2);
}

// ---------------------------------------------------------------------------
// Kernel 1: row-normalize s,t; write s,t (fp32 out) + s16/t16 (k-pair words);
// positive logit col 0.
// ---------------------------------------------------------------------------
__global__ void norm_kernel(const float* __restrict__ sr,
                            const float* __restrict__ tr,
                            float* __restrict__ out) {
    int n = blockIdx.x;
    int tid = threadIdx.x;
    const float4* s4 = (const float4*)(sr + (size_t)n * DIMK);
    const float4* t4 = (const float4*)(tr + (size_t)n * DIMK);
    float4 a = s4[tid];
    float4 b = t4[tid];
    float ss = a.x * a.x + a.y * a.y + a.z * a.z + a.w * a.w;
    float tt = b.x * b.x + b.y * b.y + b.z * b.z + b.w * b.w;
    float st = a.x * b.x + a.y * b.y + a.z * b.z + a.w * b.w;

    __shared__ float r0[256], r1[256], r2[256];
    r0[tid] = ss; r1[tid] = tt; r2[tid] = st;
    __syncthreads();
    #pragma unroll
    for (int s = 128; s > 0; s >>= 1) {
        if (tid < s) { r0[tid] += r0[tid + s]; r1[tid] += r1[tid + s]; r2[tid] += r2[tid + s]; }
        __syncthreads();
    }
    float ns = sqrtf(r0[0]);
    float nt = sqrtf(r1[0]);
    float inv_s = 1.0f / fmaxf(ns, 1e-12f);
    float inv_t = 1.0f / fmaxf(nt, 1e-12f);

    float4 so = make_float4(a.x * inv_s, a.y * inv_s, a.z * inv_s, a.w * inv_s);
    float4 to = make_float4(b.x * inv_t, b.y * inv_t, b.z * inv_t, b.w * inv_t);
    ((float4*)(out + OFF_S + (size_t)n * DIMK))[tid] = so;
    ((float4*)(out + OFF_T + (size_t)n * DIMK))[tid] = to;

    uint2 ws = make_uint2(f16x2_pack(so.x, so.y), f16x2_pack(so.z, so.w));
    uint2 wt = make_uint2(f16x2_pack(to.x, to.y), f16x2_pack(to.z, to.w));
    ((uint2*)(g_s16 + (size_t)n * NKP))[tid] = ws;
    ((uint2*)(g_t16 + (size_t)n * NKP))[tid] = wt;

    if (tid == 0) {
        float sp = r2[0] * inv_s * inv_t;
        out[OFF_SI + (size_t)n * LDC1] = sp * (1.0f / 0.07f);
    }
}

// ---------------------------------------------------------------------------
// Kernel 1b: build the B stage image. One CTA per (chunk c, panel p).
// Reads fp32 src [DIMK][CC], packs fp16 k-pair words, stores into smem with
// the EXACT R14 fill addressing (swizzle applied), writes image coalesced.
// ---------------------------------------------------------------------------
__global__ __launch_bounds__(512, 2)
void conv_b_img(const float* __restrict__ src, char* __restrict__ img) {
    __shared__ __align__(16) char stage[BIMG_CHUNK_BYTES];
    int c = blockIdx.x;   // k-chunk (0..31)
    int p = blockIdx.y;   // n-panel (0..63)
    int tid = threadIdx.x;

    int kpl = tid >> 5;            // 0..15
    int n8  = (tid & 31) * 8;
    int kp  = c * 16 + kpl;
    const float* s0 = src + (size_t)(2 * kp) * CC + p * 256 + n8;
    const float* s1 = s0 + CC;
    float4 a0 = *(const float4*)s0;
    float4 a1 = *(const float4*)(s0 + 4);
    float4 b0 = *(const float4*)s1;
    float4 b1 = *(const float4*)(s1 + 4);

    int bfn2 = n8 >> 4;
    int posB = ((n8 >> 3) & 1) * 2 + ((kpl >> 2) & 1);
    int baseB = ((kpl >> 3) * 16 + bfn2) * 512 + posB * 4;
    int slB16 = (kpl & 3) * 16;
    int swB = (bfn2 & 7) << 4;

    float l0[8] = {a0.x, a0.y, a0.z, a0.w, a1.x, a1.y, a1.z, a1.w};
    float l1[8] = {b0.x, b0.y, b0.z, b0.w, b1.x, b1.y, b1.z, b1.w};
    #pragma unroll
    for (int j = 0; j < 8; j++)
        *(uint32_t*)(stage + baseB + ((slB16 + j * 64) ^ swB)) = f16x2_pack(l0[j], l1[j]);
    __syncthreads();

    char* dst = img + (size_t)p * BIMG_PANEL_BYTES + (size_t)c * BIMG_CHUNK_BYTES;
    ((uint4*)dst)[tid]       = ((const uint4*)stage)[tid];
    ((uint4*)dst)[tid + 512] = ((const uint4*)stage)[tid + 512];
}

// ---------------------------------------------------------------------------
// Kernel 2: fused output fills (tea_img one-hot, tea_text zeros)
// ---------------------------------------------------------------------------
__global__ void fill_outputs(float* __restrict__ out) {
    size_t gtid = (size_t)blockIdx.x * blockDim.x + threadIdx.x;
    const size_t gstride = (size_t)gridDim.x * blockDim.x;

    {
        size_t total4 = (size_t)NROWS * LDC1 / 4;
        unsigned int m = (unsigned int)((4 * gtid) % LDC1);
        const unsigned int inc = (unsigned int)((4 * gstride) % LDC1);
        float4* base = (float4*)(out + OFF_TI);
        for (size_t i = gtid; i < total4; i += gstride) {
            float4 v = make_float4(0.f, 0.f, 0.f, 0.f);
            unsigned int j = (m == 0) ? 0u : (unsigned int)LDC1 - m;
            if (j < 4) (&v.x)[j] = 1.0f;
            base[i] = v;
            m += inc; if (m >= (unsigned int)LDC1) m -= (unsigned int)LDC1;
        }
    }
    {
        size_t total4 = (size_t)NROWS * CC / 4;
        float4 z = make_float4(0.f, 0.f, 0.f, 0.f);
        float4* base = (float4*)(out + OFF_TT);
        for (size_t i = gtid; i < total4; i += gstride)
            base[i] = z;
    }
}

// ---------------------------------------------------------------------------
// Kernel 4: FP16 mma GEMM, CTA 128x256, 512 threads (16 warps, warp 32x64).
// A16 [m][kp] (k-pair words): 1 LDG.128 + 4 STS per thread per chunk.
// B via cp.async from pre-swizzled image: 2 x 16B per thread per chunk,
// async-overlapped with compute. Compute side identical to R14.
// WRITEC=1: C = scale * A*B. WRITEC=0: per-row TOP-2 partials only.
// SMEM: stage = A 8KB + B 16KB = 24KB, double buffered (48KB).
// ---------------------------------------------------------------------------
#define TBUF 24576
#define TOB  8192

template<int WRITEC>
__global__ __launch_bounds__(512, 1)
void gemm_fp16(const uint32_t* __restrict__ A16, const char* __restrict__ Bimg,
               float* __restrict__ Cout, int ldc, float scale) {
    extern __shared__ char smc[];
    const uint32_t sb = smem_u32(smc);

    const int tid  = threadIdx.x;
    const int lane = tid & 31;
    const int wid  = tid >> 5;
    const int wm   = wid & 3;    // 4 m-warps x 32 rows
    const int wn   = wid >> 2;   // 4 n-warps x 64 cols
    const int mbase = blockIdx.y * 128;
    const int nbase = blockIdx.x * 256;

    // --- A fill meta: tid -> m (0..127), kpb in {0,4,8,12} ---
    const int am  = tid >> 2;
    const int kpb = (tid & 3) * 4;
    const uint32_t* aptr = A16 + (size_t)(mbase + am) * NKP + kpb;
    const int afm = am >> 4, amr = am & 15;
    const int afk = kpb >> 3;
    const int baseA = (afk * 8 + afm) * 512 + ((amr >> 3) + 2 * ((kpb >> 2) & 1)) * 4;
    const int slA16 = (amr & 7) * 4 * 16;
    const int swA = afk << 4;

    // --- B copy meta ---
    const char* bsrc = Bimg + (size_t)blockIdx.x * BIMG_PANEL_BYTES + tid * 16;
    const uint32_t bdst = sb + TOB + tid * 16;

    float c[2][8][4];
    #pragma unroll
    for (int i = 0; i < 2; i++)
        #pragma unroll
        for (int j = 0; j < 8; j++)
            #pragma unroll
            for (int r = 0; r < 4; r++) c[i][j][r] = 0.0f;

    const int lane16 = lane * 16;

    uint4 wa;

    // prologue: chunk 0 -> buffer 0
    cp16(bdst, bsrc);
    cp16(bdst + 8192, bsrc + 8192);
    CP_COMMIT();
    wa = *(const uint4*)aptr;
    {
        char* buf = smc;
        *(uint32_t*)(buf + baseA + ((slA16     ) ^ swA)) = wa.x;
        *(uint32_t*)(buf + baseA + ((slA16 + 16) ^ swA)) = wa.y;
        *(uint32_t*)(buf + baseA + ((slA16 + 32) ^ swA)) = wa.z;
        *(uint32_t*)(buf + baseA + ((slA16 + 48) ^ swA)) = wa.w;
    }
    CP_WAIT0();
    __syncthreads();

    for (int kt = 0; kt < 32; kt++) {
        char* cur = smc + (kt & 1) * TBUF;
        char* nxt = smc + ((kt & 1) ^ 1) * TBUF;
        const uint32_t nb = bdst + ((kt & 1) ^ 1) * TBUF;
        if (kt < 31) {
            // async B copy for chunk kt+1 (overlaps the MMAs below)
            const char* g = bsrc + (size_t)(kt + 1) * BIMG_CHUNK_BYTES;
            cp16(nb, g);
            cp16(nb + 8192, g + 8192);
            CP_COMMIT();
            wa = *(const uint4*)(aptr + (size_t)(kt + 1) * 16);
        }
        #pragma unroll
        for (int fk = 0; fk < 2; fk++) {
            uint4 ahf[2], bhf[4];
            #pragma unroll
            for (int i = 0; i < 2; i++) {
                int off = (fk * 8 + wm * 2 + i) * 512 + (lane16 ^ (fk << 4));
                ahf[i] = *(const uint4*)(cur + off);
            }
            #pragma unroll
            for (int j = 0; j < 4; j++) {
                int fn2 = 4 * wn + j;
                int off = TOB + (fk * 16 + fn2) * 512 + (lane16 ^ ((fn2 & 7) << 4));
                bhf[j] = *(const uint4*)(cur + off);
            }
            #pragma unroll
            for (int i = 0; i < 2; i++)
                #pragma unroll
                for (int j = 0; j < 4; j++) {
                    mma16(c[i][2 * j],     ahf[i], bhf[j].x, bhf[j].y);
                    mma16(c[i][2 * j + 1], ahf[i], bhf[j].z, bhf[j].w);
                }
        }
        if (kt < 31) {
            *(uint32_t*)(nxt + baseA + ((slA16     ) ^ swA)) = wa.x;
            *(uint32_t*)(nxt + baseA + ((slA16 + 16) ^ swA)) = wa.y;
            *(uint32_t*)(nxt + baseA + ((slA16 + 32) ^ swA)) = wa.z;
            *(uint32_t*)(nxt + baseA + ((slA16 + 48) ^ swA)) = wa.w;
            CP_WAIT0();
        }
        __syncthreads();
    }

    if (WRITEC) {
        #pragma unroll
        for (int i = 0; i < 2; i++) {
            int r0 = mbase + wm * 32 + i * 16 + (lane >> 2);
            #pragma unroll
            for (int jn = 0; jn < 8; jn++) {
                int col = nbase + wn * 64 + jn * 8 + (lane & 3) * 2;
                size_t o = (size_t)r0 * ldc + col;
                Cout[o]     = c[i][jn][0] * scale;
                Cout[o + 1] = c[i][jn][1] * scale;
                size_t o2 = o + (size_t)8 * ldc;
                Cout[o2]     = c[i][jn][2] * scale;
                Cout[o2 + 1] = c[i][jn][3] * scale;
            }
        }
    } else {
        float* rv1 = (float*)smc;
        int*   rc1 = (int*)(smc + 2048);
        float* rv2 = (float*)(smc + 4096);
        int*   rc2 = (int*)(smc + 6144);
        #pragma unroll
        for (int i = 0; i < 2; i++) {
            Top2 a, b;
            t2_init(a); t2_init(b);
            #pragma unroll
            for (int jn = 0; jn < 8; jn++) {
                int col = wn * 64 + jn * 8 + (lane & 3) * 2;
                t2_upd(a, c[i][jn][0], col);
                t2_upd(a, c[i][jn][1], col + 1);
                t2_upd(b, c[i][jn][2], col);
                t2_upd(b, c[i][jn][3], col + 1);
            }
            t2_merge_shfl(a, 1); t2_merge_shfl(a, 2);
            t2_merge_shfl(b, 1); t2_merge_shfl(b, 2);
            if ((lane & 3) == 0) {
                int rA = wm * 32 + i * 16 + (lane >> 2);
                rv1[rA * 4 + wn] = a.v1; rc1[rA * 4 + wn] = a.c1;
                rv2[rA * 4 + wn] = a.v2; rc2[rA * 4 + wn] = a.c2;
                int rB = rA + 8;
                rv1[rB * 4 + wn] = b.v1; rc1[rB * 4 + wn] = b.c1;
                rv2[rB * 4 + wn] = b.v2; rc2[rB * 4 + wn] = b.c2;
            }
        }
        __syncthreads();
        if (tid < 128) {
            Top2 t;
            t2_init(t);
            #pragma unroll
            for (int w = 0; w < 4; w++) {
                t2_upd(t, rv1[tid * 4 + w], rc1[tid * 4 + w]);
                t2_upd(t, rv2[tid * 4 + w], rc2[tid * 4 + w]);
            }
            size_t o = ((size_t)(mbase + tid) * NBLK + blockIdx.x) * 2;
            g_pmax[o]     = t.v1;  g_parg[o]     = nbase + t.c1;
            g_pmax[o + 1] = t.v2;  g_parg[o + 1] = nbase + t.c2;
        }
    }
}

// ---------------------------------------------------------------------------
// Kernel 5: candidate refine. fp16 top-2 partials -> threshold max-0.05
// (>100 sigma of fp16 dot error) -> exact fp32 re-dot -> exact argmax + exact
// softmax over survivors (others underflow to exact fp32 zero at TEMP=1e-4).
// ---------------------------------------------------------------------------
__global__ void argmax_refine(const float* __restrict__ t,
                              const float* __restrict__ cls,
                              float* __restrict__ out) {
    int n = blockIdx.x;
    int tid = threadIdx.x;
    __shared__ float pv[NBLK * 2];
    __shared__ int   pi[NBLK * 2];
    for (int i = tid; i < NBLK * 2; i += 256) {
        pv[i] = g_pmax[(size_t)n * NBLK * 2 + i];
        pi[i] = g_parg[(size_t)n * NBLK * 2 + i];
    }
    __syncthreads();
    __shared__ int cand[MAXC];
    __shared__ int ncand_s;
    if (tid == 0) {
        float m = -3.4e38f;
        for (int i = 0; i < NBLK * 2; i++) m = fmaxf(m, pv[i]);
        float thr = m - 0.05f;
        int nc = 0;
        for (int i = 0; i < NBLK * 2 && nc < MAXC; i++)
            if (pv[i] >= thr) cand[nc++] = pi[i];
        ncand_s = nc;
    }
    __syncthreads();
    int nc = ncand_s;

    __shared__ float ev[MAXC];
    __shared__ float red[256];
    const float* trow = t + (size_t)n * DIMK;
    for (int k = 0; k < nc; k++) {
        int col = cand[k];
        float part = 0.0f;
        for (int d = tid; d < DIMK; d += 256)
            part += trow[d] * cls[(size_t)d * CC + col];
        red[tid] = part;
        __syncthreads();
        #pragma unroll
        for (int s = 128; s > 0; s >>= 1) {
            if (tid < s) red[tid] += red[tid + s];
            __syncthreads();
        }
        if (tid == 0) ev[k] = red[0];
        __syncthreads();
    }

    if (tid == 0) {
        float v1 = -3.4e38f;
        int best = 0x7fffffff;
        for (int k = 0; k < nc; k++) {
            if (ev[k] > v1 || (ev[k] == v1 && cand[k] < best)) { v1 = ev[k]; best = cand[k]; }
        }
        g_labels[n] = best;
        float x1 = v1 / 1e-4f;
        float sum = 0.0f;
        for (int k = 0; k < nc; k++)
            sum += expf(ev[k] / 1e-4f - x1);
        float inv = 1.0f / sum;
        for (int k = 0; k < nc; k++)
            out[OFF_TT + (size_t)n * CC + cand[k]] = expf(ev[k] / 1e-4f - x1) * inv;
    }
}

// ---------------------------------------------------------------------------
// Kernel 6: scatter t rows into per-cluster sums/counts
// ---------------------------------------------------------------------------
__global__ void scatter_kernel(const float* __restrict__ t) {
    int n = blockIdx.x;
    int lab = g_labels[n];
    const float* trow = t + (size_t)n * DIMK;
    for (int d = threadIdx.x; d < DIMK; d += 256)
        atomicAdd(&g_sums[(size_t)d * CC + lab], trow[d]);
    if (threadIdx.x == 0)
        atomicAdd(&g_counts[lab], 1.0f);
}

// ---------------------------------------------------------------------------
// Kernel 7: EMA queue update -> new_queue [DIM, C].
// Reads g_sums unconditionally (coalesced); re-zeroes only present columns.
// ---------------------------------------------------------------------------
__global__ void update_queue(const float* __restrict__ queue,
                             const int* __restrict__ qptr,
                             float* __restrict__ outq) {
    size_t idx = (size_t)blockIdx.x * blockDim.x + threadIdx.x;
    int c = (int)(idx & (CC - 1));
    float cnt = g_counts[c];
    float q = queue[idx];
    float sv = g_sums[idx];
    bool present = cnt > 0.0f;
    if (present) g_sums[idx] = 0.0f;
    float z = sv / fmaxf(cnt, 1.0f);
    bool init = qptr[c] > 0;
    float ema = 0.99f * q + 0.01f * z;
    float ncol = init ? ema : z;
    outq[idx] = present ? ncol : q;
}

// ---------------------------------------------------------------------------
// Kernel 8: new_ptr; resets g_counts (self-cleaning)
// ---------------------------------------------------------------------------
__global__ void update_ptr(const int* __restrict__ qptr, float* __restrict__ outp) {
    int c = blockIdx.x * blockDim.x + threadIdx.x;
    if (c < CC) {
        float cnt = g_counts[c];
        outp[c] = (cnt > 0.0f) ? 1.0f : (float)qptr[c];
        g_counts[c] = 0.0f;
    }
}

// ---------------------------------------------------------------------------
extern "C" void kernel_launch(void* const* d_in, const int* in_sizes, int n_in,
                              void* d_out, int out_size) {
    const float* s_raw      = (const float*)d_in[0];
    const float* t_raw      = (const float*)d_in[1];
    const float* queue      = (const float*)d_in[2];
    const float* classifier = (const float*)d_in[3];
    const int*   qptr       = (const int*)d_in[4];
    float* out = (float*)d_out;

    cudaFuncSetAttribute(gemm_fp16<1>,
                         cudaFuncAttributeMaxDynamicSharedMemorySize, 2 * TBUF);
    cudaFuncSetAttribute(gemm_fp16<0>,
                         cudaFuncAttributeMaxDynamicSharedMemorySize, 2 * TBUF);

    char* dqimg;  cudaGetSymbolAddress((void**)&dqimg, g_qimg);
    char* dcimg;  cudaGetSymbolAddress((void**)&dcimg, g_cimg);
    uint32_t* ds16;  cudaGetSymbolAddress((void**)&ds16, g_s16);
    uint32_t* dt16;  cudaGetSymbolAddress((void**)&dt16, g_t16);

    norm_kernel<<<NROWS, 256>>>(s_raw, t_raw, out);
    conv_b_img<<<dim3(32, 64), 512>>>(queue, dqimg);
    conv_b_img<<<dim3(32, 64), 512>>>(classifier, dcimg);
    fill_outputs<<<2048, 256>>>(out);

    dim3 gemm_grid(CC / 256, NROWS / 128);

    // student GEMMs: single-pass fp16 (2^-11 roundoff, same as TF32; ~3e-4)
    gemm_fp16<1><<<gemm_grid, 512, 2 * TBUF>>>(ds16, dqimg,
                                               out + OFF_SI + 1, LDC1, 1.0f / 0.07f);
    gemm_fp16<1><<<gemm_grid, 512, 2 * TBUF>>>(ds16, dcimg,
                                               out + OFF_ST, CC, 1.0f / 0.07f);
    // teacher: single-pass fp16 screening, top-2 partials only
    gemm_fp16<0><<<gemm_grid, 512, 2 * TBUF>>>(dt16, dcimg,
                                               nullptr, 0, 1.0f);

    // exact-fp32 refine: labels + true softmax probs for near-tie rows
    argmax_refine<<<NROWS, 256>>>(out + OFF_T, classifier, out);

    scatter_kernel<<<NROWS, 256>>>(out + OFF_T);
    update_queue<<<(DIMK * CC) / 256, 256>>>(queue, qptr, out + OFF_Q);
    update_ptr<<<CC / 256, 256>>>(qptr, out + OFF_P);
}

// round 16
// speedup vs baseline: 1.7168x; 1.0711x over previous
#include <cuda_runtime.h>
#include <math.h>
#include <stdint.h>

// Problem constants
#define NROWS 4096
#define DIMK  1024
#define NKP   512            // DIMK/2 k-pair words
#define CC    16384
#define LDC1  (CC + 1)

// Output layout offsets (floats), tuple order flattened row-major
#define OFF_SI 0ULL                                  // logit_stu_img [N, C+1]
#define OFF_TI (OFF_SI + (size_t)NROWS * LDC1)       // logit_tea_img [N, C+1]
#define OFF_ST (OFF_TI + (size_t)NROWS * LDC1)       // logit_stu_text [N, C]
#define OFF_TT (OFF_ST + (size_t)NROWS * CC)         // logit_tea_text [N, C]
#define OFF_S  (OFF_TT + (size_t)NROWS * CC)         // s [N, DIM]
#define OFF_T  (OFF_S  + (size_t)NROWS * DIMK)       // t [N, DIM]
#define OFF_Q  (OFF_T  + (size_t)NROWS * DIMK)       // new_queue [DIM, C]
#define OFF_P  (OFF_Q  + (size_t)DIMK * CC)          // new_ptr [C]

#define NBLK 64   // teacher GEMM n-tiles (CC/256)
#define MAXC 32   // refine candidate cap

// B image: per n-panel (256 cols) per 32-k chunk, one 16KB pre-swizzled block.
#define BIMG_CHUNK 16384
#define BIMG_PANEL ((size_t)32 * BIMG_CHUNK)
// A image: per m-panel (128 rows) per 32-k chunk, one 8KB pre-swizzled block.
#define AIMG_CHUNK 8192
#define AIMG_PANEL ((size_t)32 * AIMG_CHUNK)

// Scratch (static device globals; no allocation).
__device__ __align__(16) float g_sums[(size_t)DIMK * CC];   // [DIM][C]
__device__ float g_counts[CC];
__device__ int   g_labels[NROWS];
__device__ float g_pmax[(size_t)NROWS * NBLK * 2];
__device__ int   g_parg[(size_t)NROWS * NBLK * 2];
// fp16 operands
__device__ __align__(16) uint32_t g_s16[(size_t)NROWS * NKP];   // [m][kp]
__device__ __align__(16) uint32_t g_t16[(size_t)NROWS * NKP];
__device__ __align__(16) char g_qimg[(size_t)NBLK * BIMG_PANEL];       // 32MB
__device__ __align__(16) char g_cimg[(size_t)NBLK * BIMG_PANEL];
__device__ __align__(16) char g_simg[(size_t)(NROWS / 128) * AIMG_PANEL]; // 8MB
__device__ __align__(16) char g_timg[(size_t)(NROWS / 128) * AIMG_PANEL];

// ---------------------------------------------------------------------------
// helpers
// ---------------------------------------------------------------------------
__device__ __forceinline__ uint32_t f16x2_pack(float lo, float hi) {
    uint32_t r;
    asm("cvt.rn.f16x2.f32 %0, %1, %2;" : "=r"(r) : "f"(hi), "f"(lo));
    return r;
}
__device__ __forceinline__ uint32_t smem_u32(const void* p) {
    uint32_t a;
    asm("{ .reg .u64 t; cvta.to.shared.u64 t, %1; cvt.u32.u64 %0, t; }"
        : "=r"(a) : "l"(p));
    return a;
}
__device__ __forceinline__ void cp16(uint32_t sm, const void* g) {
    asm volatile("cp.async.cg.shared.global [%0], [%1], 16;" :: "r"(sm), "l"(g) : "memory");
}
#define CP_COMMIT() asm volatile("cp.async.commit_group;" ::: "memory")
#define CP_WAIT(n)  asm volatile("cp.async.wait_group %0;" :: "n"(n) : "memory")

__device__ __forceinline__ void mma16(float* c, const uint4& a, uint32_t b0, uint32_t b1) {
    asm volatile(
        "mma.sync.aligned.m16n8k16.row.col.f32.f16.f16.f32 "
        "{%0,%1,%2,%3}, {%4,%5,%6,%7}, {%8,%9}, {%0,%1,%2,%3};\n"
        : "+f"(c[0]), "+f"(c[1]), "+f"(c[2]), "+f"(c[3])
        : "r"(a.x), "r"(a.y), "r"(a.z), "r"(a.w), "r"(b0), "r"(b1));
}

struct Top2 { float v1, v2; int c1, c2; };
__device__ __forceinline__ void t2_init(Top2& t) {
    t.v1 = -3.4e38f; t.v2 = -3.4e38f; t.c1 = 0x7fffffff; t.c2 = 0x7fffffff;
}
__device__ __forceinline__ void t2_upd(Top2& t, float v, int c) {
    if (v > t.v1 || (v == t.v1 && c < t.c1)) {
        t.v2 = t.v1; t.c2 = t.c1; t.v1 = v; t.c1 = c;
    } else if (v > t.v2 || (v == t.v2 && c < t.c2)) {
        t.v2 = v; t.c2 = c;
    }
}
__device__ __forceinline__ void t2_merge_shfl(Top2& t, int d) {
    float ov1 = __shfl_xor_sync(0xffffffffu, t.v1, d);
    int   oc1 = __shfl_xor_sync(0xffffffffu, t.c1, d);
    float ov2 = __shfl_xor_sync(0xffffffffu, t.v2, d);
    int   oc2 = __shfl_xor_sync(0xffffffffu, t.c2, d);
    t2_upd(t, ov1, oc1);
    t2_upd(t, ov2, oc2);
}

// ---------------------------------------------------------------------------
// Kernel 1: row-normalize s,t; write s,t (fp32 out) + s16/t16 (k-pair words);
// positive logit col 0.
// ---------------------------------------------------------------------------
__global__ void norm_kernel(const float* __restrict__ sr,
                            const float* __restrict__ tr,
                            float* __restrict__ out) {
    int n = blockIdx.x;
    int tid = threadIdx.x;
    const float4* s4 = (const float4*)(sr + (size_t)n * DIMK);
    const float4* t4 = (const float4*)(tr + (size_t)n * DIMK);
    float4 a = s4[tid];
    float4 b = t4[tid];
    float ss = a.x * a.x + a.y * a.y + a.z * a.z + a.w * a.w;
    float tt = b.x * b.x + b.y * b.y + b.z * b.z + b.w * b.w;
    float st = a.x * b.x + a.y * b.y + a.z * b.z + a.w * b.w;

    __shared__ float r0[256], r1[256], r2[256];
    r0[tid] = ss; r1[tid] = tt; r2[tid] = st;
    __syncthreads();
    #pragma unroll
    for (int s = 128; s > 0; s >>= 1) {
        if (tid < s) { r0[tid] += r0[tid + s]; r1[tid] += r1[tid + s]; r2[tid] += r2[tid + s]; }
        __syncthreads();
    }
    float ns = sqrtf(r0[0]);
    float nt = sqrtf(r1[0]);
    float inv_s = 1.0f / fmaxf(ns, 1e-12f);
    float inv_t = 1.0f / fmaxf(nt, 1e-12f);

    float4 so = make_float4(a.x * inv_s, a.y * inv_s, a.z * inv_s, a.w * inv_s);
    float4 to = make_float4(b.x * inv_t, b.y * inv_t, b.z * inv_t, b.w * inv_t);
    ((float4*)(out + OFF_S + (size_t)n * DIMK))[tid] = so;
    ((float4*)(out + OFF_T + (size_t)n * DIMK))[tid] = to;

    uint2 ws = make_uint2(f16x2_pack(so.x, so.y), f16x2_pack(so.z, so.w));
    uint2 wt = make_uint2(f16x2_pack(to.x, to.y), f16x2_pack(to.z, to.w));
    ((uint2*)(g_s16 + (size_t)n * NKP))[tid] = ws;
    ((uint2*)(g_t16 + (size_t)n * NKP))[tid] = wt;

    if (tid == 0) {
        float sp = r2[0] * inv_s * inv_t;
        out[OFF_SI + (size_t)n * LDC1] = sp * (1.0f / 0.07f);
    }
}

// ---------------------------------------------------------------------------
// Kernel 1a: build A stage image from A16 [m][kp].  One CTA per
// (chunk c, m-panel mp); exact GEMM A-fill addressing, written coalesced.
// ---------------------------------------------------------------------------
__global__ __launch_bounds__(512, 2)
void conv_a_img(const uint32_t* __restrict__ A16, char* __restrict__ img) {
    __shared__ __align__(16) char stage[AIMG_CHUNK];
    int c  = blockIdx.x;   // k-chunk (0..31)
    int mp = blockIdx.y;   // m-panel (0..31)
    int tid = threadIdx.x;

    int am  = tid >> 2;
    int kpb = (tid & 3) * 4;
    uint4 w = *(const uint4*)(A16 + (size_t)(mp * 128 + am) * NKP + c * 16 + kpb);

    int afm = am >> 4, amr = am & 15;
    int afk = kpb >> 3;
    int baseA = (afk * 8 + afm) * 512 + ((amr >> 3) + 2 * ((kpb >> 2) & 1)) * 4;
    int slA16 = (amr & 7) * 4 * 16;
    int swA = afk << 4;
    *(uint32_t*)(stage + baseA + ((slA16     ) ^ swA)) = w.x;
    *(uint32_t*)(stage + baseA + ((slA16 + 16) ^ swA)) = w.y;
    *(uint32_t*)(stage + baseA + ((slA16 + 32) ^ swA)) = w.z;
    *(uint32_t*)(stage + baseA + ((slA16 + 48) ^ swA)) = w.w;
    __syncthreads();

    char* dst = img + (size_t)mp * AIMG_PANEL + (size_t)c * AIMG_CHUNK;
    ((uint4*)dst)[tid] = ((const uint4*)stage)[tid];
}

// ---------------------------------------------------------------------------
// Kernel 1b: build B stage image (exact R14 B-fill addressing)
// ---------------------------------------------------------------------------
__global__ __launch_bounds__(512, 2)
void conv_b_img(const float* __restrict__ src, char* __restrict__ img) {
    __shared__ __align__(16) char stage[BIMG_CHUNK];
    int c = blockIdx.x;   // k-chunk (0..31)
    int p = blockIdx.y;   // n-panel (0..63)
    int tid = threadIdx.x;

    int kpl = tid >> 5;            // 0..15
    int n8  = (tid & 31) * 8;
    int kp  = c * 16 + kpl;
    const float* s0 = src + (size_t)(2 * kp) * CC + p * 256 + n8;
    const float* s1 = s0 + CC;
    float4 a0 = *(const float4*)s0;
    float4 a1 = *(const float4*)(s0 + 4);
    float4 b0 = *(const float4*)s1;
    float4 b1 = *(const float4*)(s1 + 4);

    int bfn2 = n8 >> 4;
    int posB = ((n8 >> 3) & 1) * 2 + ((kpl >> 2) & 1);
    int baseB = ((kpl >> 3) * 16 + bfn2) * 512 + posB * 4;
    int slB16 = (kpl & 3) * 16;
    int swB = (bfn2 & 7) << 4;

    float l0[8] = {a0.x, a0.y, a0.z, a0.w, a1.x, a1.y, a1.z, a1.w};
    float l1[8] = {b0.x, b0.y, b0.z, b0.w, b1.x, b1.y, b1.z, b1.w};
    #pragma unroll
    for (int j = 0; j < 8; j++)
        *(uint32_t*)(stage + baseB + ((slB16 + j * 64) ^ swB)) = f16x2_pack(l0[j], l1[j]);
    __syncthreads();

    char* dst = img + (size_t)p * BIMG_PANEL + (size_t)c * BIMG_CHUNK;
    ((uint4*)dst)[tid]       = ((const uint4*)stage)[tid];
    ((uint4*)dst)[tid + 512] = ((const uint4*)stage)[tid + 512];
}

// ---------------------------------------------------------------------------
// Kernel 2: fused output fills (tea_img one-hot, tea_text zeros)
// ---------------------------------------------------------------------------
__global__ void fill_outputs(float* __restrict__ out) {
    size_t gtid = (size_t)blockIdx.x * blockDim.x + threadIdx.x;
    const size_t gstride = (size_t)gridDim.x * blockDim.x;

    {
        size_t total4 = (size_t)NROWS * LDC1 / 4;
        unsigned int m = (unsigned int)((4 * gtid) % LDC1);
        const unsigned int inc = (unsigned int)((4 * gstride) % LDC1);
        float4* base = (float4*)(out + OFF_TI);
        for (size_t i = gtid; i < total4; i += gstride) {
            float4 v = make_float4(0.f, 0.f, 0.f, 0.f);
            unsigned int j = (m == 0) ? 0u : (unsigned int)LDC1 - m;
            if (j < 4) (&v.x)[j] = 1.0f;
            base[i] = v;
            m += inc; if (m >= (unsigned int)LDC1) m -= (unsigned int)LDC1;
        }
    }
    {
        size_t total4 = (size_t)NROWS * CC / 4;
        float4 z = make_float4(0.f, 0.f, 0.f, 0.f);
        float4* base = (float4*)(out + OFF_TT);
        for (size_t i = gtid; i < total4; i += gstride)
            base[i] = z;
    }
}

// ---------------------------------------------------------------------------
// Kernel 4: FP16 mma GEMM, CTA 128x256, 512 threads (16 warps, warp 32x64).
// Both operands via cp.async from pre-swizzled images: 3 x 16B per thread per
// chunk, 3-stage pipeline (wait_group 1 steady state) — zero LDG/STS/ALU in
// the fill path. Compute side identical to R14/R15.
// WRITEC=1: C = scale * A*B. WRITEC=0: per-row TOP-2 partials only.
// SMEM: stage = A 8KB + B 16KB = 24KB, 3 stages (72KB).
// ---------------------------------------------------------------------------
#define TBUF 24576
#define TOB  8192
#define GSMEM (3 * TBUF)

template<int WRITEC>
__global__ __launch_bounds__(512, 1)
void gemm_fp16(const char* __restrict__ Aimg, const char* __restrict__ Bimg,
               float* __restrict__ Cout, int ldc, float scale) {
    extern __shared__ char smc[];
    const uint32_t sb = smem_u32(smc);

    const int tid  = threadIdx.x;
    const int lane = tid & 31;
    const int wid  = tid >> 5;
    const int wm   = wid & 3;    // 4 m-warps x 32 rows
    const int wn   = wid >> 2;   // 4 n-warps x 64 cols
    const int mbase = blockIdx.y * 128;
    const int nbase = blockIdx.x * 256;

    const char* asrc = Aimg + (size_t)blockIdx.y * AIMG_PANEL + tid * 16;
    const char* bsrc = Bimg + (size_t)blockIdx.x * BIMG_PANEL + tid * 16;
    const uint32_t t16o = tid * 16;

    float c[2][8][4];
    #pragma unroll
    for (int i = 0; i < 2; i++)
        #pragma unroll
        for (int j = 0; j < 8; j++)
            #pragma unroll
            for (int r = 0; r < 4; r++) c[i][j][r] = 0.0f;

    const int lane16 = lane * 16;

    // issue stage for chunk kc into buffer kc % 3
    #define ISSUE(kc) do { \
        uint32_t stg = sb + ((kc) % 3) * TBUF; \
        cp16(stg + t16o, asrc + (size_t)(kc) * AIMG_CHUNK); \
        cp16(stg + TOB + t16o, bsrc + (size_t)(kc) * BIMG_CHUNK); \
        cp16(stg + TOB + 8192 + t16o, bsrc + (size_t)(kc) * BIMG_CHUNK + 8192); \
        CP_COMMIT(); \
    } while (0)

    ISSUE(0);
    ISSUE(1);

    for (int kt = 0; kt < 32; kt++) {
        if (kt < 30) CP_WAIT(1); else CP_WAIT(0);
        __syncthreads();
        if (kt + 2 < 32) ISSUE(kt + 2);

        char* cur = smc + (kt % 3) * TBUF;
        #pragma unroll
        for (int fk = 0; fk < 2; fk++) {
            uint4 ahf[2], bhf[4];
            #pragma unroll
            for (int i = 0; i < 2; i++) {
                int off = (fk * 8 + wm * 2 + i) * 512 + (lane16 ^ (fk << 4));
                ahf[i] = *(const uint4*)(cur + off);
            }
            #pragma unroll
            for (int j = 0; j < 4; j++) {
                int fn2 = 4 * wn + j;
                int off = TOB + (fk * 16 + fn2) * 512 + (lane16 ^ ((fn2 & 7) << 4));
                bhf[j] = *(const uint4*)(cur + off);
            }
            #pragma unroll
            for (int i = 0; i < 2; i++)
                #pragma unroll
                for (int j = 0; j < 4; j++) {
                    mma16(c[i][2 * j],     ahf[i], bhf[j].x, bhf[j].y);
                    mma16(c[i][2 * j + 1], ahf[i], bhf[j].z, bhf[j].w);
                }
        }
    }
    __syncthreads();
    #undef ISSUE

    if (WRITEC) {
        #pragma unroll
        for (int i = 0; i < 2; i++) {
            int r0 = mbase + wm * 32 + i * 16 + (lane >> 2);
            #pragma unroll
            for (int jn = 0; jn < 8; jn++) {
                int col = nbase + wn * 64 + jn * 8 + (lane & 3) * 2;
                size_t o = (size_t)r0 * ldc + col;
                Cout[o]     = c[i][jn][0] * scale;
                Cout[o + 1] = c[i][jn][1] * scale;
                size_t o2 = o + (size_t)8 * ldc;
                Cout[o2]     = c[i][jn][2] * scale;
                Cout[o2 + 1] = c[i][jn][3] * scale;
            }
        }
    } else {
        float* rv1 = (float*)smc;
        int*   rc1 = (int*)(smc + 2048);
        float* rv2 = (float*)(smc + 4096);
        int*   rc2 = (int*)(smc + 6144);
        #pragma unroll
        for (int i = 0; i < 2; i++) {
            Top2 a, b;
            t2_init(a); t2_init(b);
            #pragma unroll
            for (int jn = 0; jn < 8; jn++) {
                int col = wn * 64 + jn * 8 + (lane & 3) * 2;
                t2_upd(a, c[i][jn][0], col);
                t2_upd(a, c[i][jn][1], col + 1);
                t2_upd(b, c[i][jn][2], col);
                t2_upd(b, c[i][jn][3], col + 1);
            }
            t2_merge_shfl(a, 1); t2_merge_shfl(a, 2);
            t2_merge_shfl(b, 1); t2_merge_shfl(b, 2);
            if ((lane & 3) == 0) {
                int rA = wm * 32 + i * 16 + (lane >> 2);
                rv1[rA * 4 + wn] = a.v1; rc1[rA * 4 + wn] = a.c1;
                rv2[rA * 4 + wn] = a.v2; rc2[rA * 4 + wn] = a.c2;
                int rB = rA + 8;
                rv1[rB * 4 + wn] = b.v1; rc1[rB * 4 + wn] = b.c1;
                rv2[rB * 4 + wn] = b.v2; rc2[rB * 4 + wn] = b.c2;
            }
        }
        __syncthreads();
        if (tid < 128) {
            Top2 t;
            t2_init(t);
            #pragma unroll
            for (int w = 0; w < 4; w++) {
                t2_upd(t, rv1[tid * 4 + w], rc1[tid * 4 + w]);
                t2_upd(t, rv2[tid * 4 + w], rc2[tid * 4 + w]);
            }
            size_t o = ((size_t)(mbase + tid) * NBLK + blockIdx.x) * 2;
            g_pmax[o]     = t.v1;  g_parg[o]     = nbase + t.c1;
            g_pmax[o + 1] = t.v2;  g_parg[o + 1] = nbase + t.c2;
        }
    }
}

// ---------------------------------------------------------------------------
// Kernel 5: candidate refine. fp16 top-2 partials -> threshold max-0.05
// (>100 sigma of fp16 dot error) -> exact fp32 re-dot -> exact argmax + exact
// softmax over survivors (others underflow to exact fp32 zero at TEMP=1e-4).
// ---------------------------------------------------------------------------
__global__ void argmax_refine(const float* __restrict__ t,
                              const float* __restrict__ cls,
                              float* __restrict__ out) {
    int n = blockIdx.x;
    int tid = threadIdx.x;
    __shared__ float pv[NBLK * 2];
    __shared__ int   pi[NBLK * 2];
    for (int i = tid; i < NBLK * 2; i += 256) {
        pv[i] = g_pmax[(size_t)n * NBLK * 2 + i];
        pi[i] = g_parg[(size_t)n * NBLK * 2 + i];
    }
    __syncthreads();
    __shared__ int cand[MAXC];
    __shared__ int ncand_s;
    if (tid == 0) {
        float m = -3.4e38f;
        for (int i = 0; i < NBLK * 2; i++) m = fmaxf(m, pv[i]);
        float thr = m - 0.05f;
        int nc = 0;
        for (int i = 0; i < NBLK * 2 && nc < MAXC; i++)
            if (pv[i] >= thr) cand[nc++] = pi[i];
        ncand_s = nc;
    }
    __syncthreads();
    int nc = ncand_s;

    __shared__ float ev[MAXC];
    __shared__ float red[256];
    const float* trow = t + (size_t)n * DIMK;
    for (int k = 0; k < nc; k++) {
        int col = cand[k];
        float part = 0.0f;
        for (int d = tid; d < DIMK; d += 256)
            part += trow[d] * cls[(size_t)d * CC + col];
        red[tid] = part;
        __syncthreads();
        #pragma unroll
        for (int s = 128; s > 0; s >>= 1) {
            if (tid < s) red[tid] += red[tid + s];
            __syncthreads();
        }
        if (tid == 0) ev[k] = red[0];
        __syncthreads();
    }

    if (tid == 0) {
        float v1 = -3.4e38f;
        int best = 0x7fffffff;
        for (int k = 0; k < nc; k++) {
            if (ev[k] > v1 || (ev[k] == v1 && cand[k] < best)) { v1 = ev[k]; best = cand[k]; }
        }
        g_labels[n] = best;
        float x1 = v1 / 1e-4f;
        float sum = 0.0f;
        for (int k = 0; k < nc; k++)
            sum += expf(ev[k] / 1e-4f - x1);
        float inv = 1.0f / sum;
        for (int k = 0; k < nc; k++)
            out[OFF_TT + (size_t)n * CC + cand[k]] = expf(ev[k] / 1e-4f - x1) * inv;
    }
}

// ---------------------------------------------------------------------------
// Kernel 6: scatter t rows into per-cluster sums/counts
// ---------------------------------------------------------------------------
__global__ void scatter_kernel(const float* __restrict__ t) {
    int n = blockIdx.x;
    int lab = g_labels[n];
    const float* trow = t + (size_t)n * DIMK;
    for (int d = threadIdx.x; d < DIMK; d += 256)
        atomicAdd(&g_sums[(size_t)d * CC + lab], trow[d]);
    if (threadIdx.x == 0)
        atomicAdd(&g_counts[lab], 1.0f);
}

// ---------------------------------------------------------------------------
// Kernel 7: EMA queue update -> new_queue [DIM, C].
// ---------------------------------------------------------------------------
__global__ void update_queue(const float* __restrict__ queue,
                             const int* __restrict__ qptr,
                             float* __restrict__ outq) {
    size_t idx = (size_t)blockIdx.x * blockDim.x + threadIdx.x;
    int c = (int)(idx & (CC - 1));
    float cnt = g_counts[c];
    float q = queue[idx];
    float sv = g_sums[idx];
    bool present = cnt > 0.0f;
    if (present) g_sums[idx] = 0.0f;
    float z = sv / fmaxf(cnt, 1.0f);
    bool init = qptr[c] > 0;
    float ema = 0.99f * q + 0.01f * z;
    float ncol = init ? ema : z;
    outq[idx] = present ? ncol : q;
}

// ---------------------------------------------------------------------------
// Kernel 8: new_ptr; resets g_counts (self-cleaning)
// ---------------------------------------------------------------------------
__global__ void update_ptr(const int* __restrict__ qptr, float* __restrict__ outp) {
    int c = blockIdx.x * blockDim.x + threadIdx.x;
    if (c < CC) {
        float cnt = g_counts[c];
        outp[c] = (cnt > 0.0f) ? 1.0f : (float)qptr[c];
        g_counts[c] = 0.0f;
    }
}

// ---------------------------------------------------------------------------
extern "C" void kernel_launch(void* const* d_in, const int* in_sizes, int n_in,
                              void* d_out, int out_size) {
    const float* s_raw      = (const float*)d_in[0];
    const float* t_raw      = (const float*)d_in[1];
    const float* queue      = (const float*)d_in[2];
    const float* classifier = (const float*)d_in[3];
    const int*   qptr       = (const int*)d_in[4];
    float* out = (float*)d_out;

    cudaFuncSetAttribute(gemm_fp16<1>,
                         cudaFuncAttributeMaxDynamicSharedMemorySize, GSMEM);
    cudaFuncSetAttribute(gemm_fp16<0>,
                         cudaFuncAttributeMaxDynamicSharedMemorySize, GSMEM);

    char* dqimg;  cudaGetSymbolAddress((void**)&dqimg, g_qimg);
    char* dcimg;  cudaGetSymbolAddress((void**)&dcimg, g_cimg);
    char* dsimg;  cudaGetSymbolAddress((void**)&dsimg, g_simg);
    char* dtimg;  cudaGetSymbolAddress((void**)&dtimg, g_timg);
    uint32_t* ds16;  cudaGetSymbolAddress((void**)&ds16, g_s16);
    uint32_t* dt16;  cudaGetSymbolAddress((void**)&dt16, g_t16);

    norm_kernel<<<NROWS, 256>>>(s_raw, t_raw, out);
    conv_a_img<<<dim3(32, 32), 512>>>(ds16, dsimg);
    conv_a_img<<<dim3(32, 32), 512>>>(dt16, dtimg);
    conv_b_img<<<dim3(32, 64), 512>>>(queue, dqimg);
    conv_b_img<<<dim3(32, 64), 512>>>(classifier, dcimg);
    fill_outputs<<<2048, 256>>>(out);

    dim3 gemm_grid(CC / 256, NROWS / 128);

    // student GEMMs: single-pass fp16 (2^-11 roundoff, same as TF32; ~3e-4)
    gemm_fp16<1><<<gemm_grid, 512, GSMEM>>>(dsimg, dqimg,
                                            out + OFF_SI + 1, LDC1, 1.0f / 0.07f);
    gemm_fp16<1><<<gemm_grid, 512, GSMEM>>>(dsimg, dcimg,
                                            out + OFF_ST, CC, 1.0f / 0.07f);
    // teacher: single-pass fp16 screening, top-2 partials only
    gemm_fp16<0><<<gemm_grid, 512, GSMEM>>>(dtimg, dcimg,
                                            nullptr, 0, 1.0f);

    // exact-fp32 refine: labels + true softmax probs for near-tie rows
    argmax_refine<<<NROWS, 256>>>(out + OFF_T, classifier, out);

    scatter_kernel<<<NROWS, 256>>>(out + OFF_T);
    update_queue<<<(DIMK * CC) / 256, 256>>>(queue, qptr, out + OFF_Q);
    update_ptr<<<CC / 256, 256>>>(qptr, out + OFF_P);
}